// round 13
// baseline (speedup 1.0000x reference)
#include <cuda_runtime.h>
#include <cuda_fp16.h>
#include <cstdint>
#include <math.h>

// Problem constants
#define TT 2048
#define DD 4096
#define NH 32
#define KH 8
#define HD 128
#define SCALE 0.08838834764831843f   // 1/sqrt(128)

// ====================== PTX helpers (base sm_103-legal only) ======================
__device__ __forceinline__ uint32_t smem_to_u32(const void* p) {
    uint32_t a;
    asm("{ .reg .u64 t; cvta.to.shared.u64 t, %1; cvt.u32.u64 %0, t; }" : "=r"(a) : "l"(p));
    return a;
}
#define CP16(sa, ga) \
    asm volatile("cp.async.cg.shared.global [%0], [%1], 16;" :: "r"(sa), "l"(ga) : "memory")
#define CP_COMMIT() asm volatile("cp.async.commit_group;" ::: "memory")
#define CP_WAIT(n)  asm volatile("cp.async.wait_group %0;" :: "n"(n) : "memory")
#define LDSM4(r, a) \
    asm volatile("ldmatrix.sync.aligned.m8n8.x4.shared.b16 {%0,%1,%2,%3}, [%4];" \
        : "=r"((r)[0]), "=r"((r)[1]), "=r"((r)[2]), "=r"((r)[3]) : "r"(a))
#define LDSM4T(r, a) \
    asm volatile("ldmatrix.sync.aligned.m8n8.x4.trans.shared.b16 {%0,%1,%2,%3}, [%4];" \
        : "=r"((r)[0]), "=r"((r)[1]), "=r"((r)[2]), "=r"((r)[3]) : "r"(a))
#define MMAH(d, a, b) \
    asm volatile("mma.sync.aligned.m16n8k16.row.col.f32.f16.f16.f32 " \
        "{%0,%1,%2,%3}, {%4,%5,%6,%7}, {%8,%9}, {%0,%1,%2,%3};" \
        : "+f"((d)[0]), "+f"((d)[1]), "+f"((d)[2]), "+f"((d)[3]) \
        : "r"((a)[0]), "r"((a)[1]), "r"((a)[2]), "r"((a)[3]), "r"((b)[0]), "r"((b)[1]))

// ====================== device scratch ======================
__device__ __half g_xh  [TT * DD];
__device__ __half g_aoh [TT * DD];
__device__ __half g_wq16[DD * DD];       // fp16 copy, natural [K,N] layout
__device__ __half g_wk16[DD * KH*HD];
__device__ __half g_wv16[DD * KH*HD];
__device__ __half g_wo16[DD * DD];
__device__ __half g_qh  [TT * NH * HD];
__device__ __half g_kh  [TT * KH * HD];
__device__ __half g_vh  [TT * KH * HD];

// ====================== fused fp32 -> fp16 convert (all 5 tensors) ============
#define F4_X  2097152
#define F4_WQ 4194304
#define F4_WK 1048576
#define F4_WV 1048576
#define F4_WO 4194304
#define F4_TOT (F4_X + F4_WQ + F4_WK + F4_WV + F4_WO)   // 12582912

__global__ void conv_all(
    const float* __restrict__ x,  const float* __restrict__ wq,
    const float* __restrict__ wk, const float* __restrict__ wv,
    const float* __restrict__ wo,
    __half* __restrict__ xh, __half* __restrict__ wqh, __half* __restrict__ wkh,
    __half* __restrict__ wvh, __half* __restrict__ woh)
{
    long long i = (long long)blockIdx.x * 256 + threadIdx.x;
    if (i >= F4_TOT) return;
    const float* s; __half* d;
    if (i < F4_X)                         { s = x;  d = xh; }
    else if (i < F4_X + F4_WQ)            { s = wq; d = wqh; i -= F4_X; }
    else if (i < F4_X + F4_WQ + F4_WK)    { s = wk; d = wkh; i -= F4_X + F4_WQ; }
    else if (i < F4_X + F4_WQ + 2*F4_WK)  { s = wv; d = wvh; i -= F4_X + F4_WQ + F4_WK; }
    else                                  { s = wo; d = woh; i -= F4_X + F4_WQ + 2*F4_WK; }
    float4 f = ((const float4*)s)[i];
    __align__(8) __half h[4] = {__float2half_rn(f.x), __float2half_rn(f.y),
                                __float2half_rn(f.z), __float2half_rn(f.w)};
    *(uint2*)(d + 4 * (size_t)i) = *(uint2*)h;
}

// ====================== mma.sync GEMM core ======================
// 128(M) x 256(N) CTA tile, BK=32, 512 threads, 16 warps (4x4), warp tile 32x64.
// A smem [M,K] (non-trans frags).  B smem [K,N] (trans frags).
#define SRA 80                         // A row stride bytes (32 halves + pad)
#define SRB3 528                       // B row stride bytes (256 halves + pad)
#define A_TILE (128 * SRA)             // 10240
#define B_TILE (32 * SRB3)             // 16896
#define STAGE_B (A_TILE + B_TILE)      // 27136
#define GEMM_SMEM (3 * STAGE_B)        // 81408

struct AccT { float a[2][8][4]; };

__device__ __forceinline__ void gemm_core(
    uint32_t sbase, const __half* pA, const __half* pB, int Kd, int Nw, AccT& A)
{
    const int tid = threadIdx.x, lane = tid & 31, wid = tid >> 5;
    const int wm = wid >> 2, wn = wid & 3;
    const int arow = tid >> 2;             // 0..127
    const uint32_t aso = (tid & 3) * 16;
    const int acol = (tid & 3) * 8;
    const int brow = tid >> 4;             // 0..31
    const int bc16 = tid & 15;

    const int nst = Kd >> 5;

    #pragma unroll
    for (int ps = 0; ps < 2; ps++) {       // prologue stages 0,1
        const int k0 = ps << 5;
        uint32_t st = sbase + ps * STAGE_B;
        CP16(st + (uint32_t)arow * SRA + aso, pA + (size_t)arow * Kd + k0 + acol);
        CP16(st + A_TILE + (uint32_t)brow * SRB3 + bc16 * 16,
             pB + (size_t)(k0 + brow) * Nw + bc16 * 8);
        CP16(st + A_TILE + (uint32_t)brow * SRB3 + (bc16 + 16) * 16,
             pB + (size_t)(k0 + brow) * Nw + (bc16 + 16) * 8);
        CP_COMMIT();
    }

    int sidx = 0;
    for (int s = 0; s < nst; s++) {
        if (s + 1 < nst) { CP_WAIT(1); } else { CP_WAIT(0); }
        __syncthreads();                   // single barrier per stage

        if (s + 2 < nst) {
            const int k0 = (s + 2) << 5;
            int lidx = sidx - 1; if (lidx < 0) lidx += 3;
            uint32_t st = sbase + lidx * STAGE_B;
            CP16(st + (uint32_t)arow * SRA + aso, pA + (size_t)arow * Kd + k0 + acol);
            CP16(st + A_TILE + (uint32_t)brow * SRB3 + bc16 * 16,
                 pB + (size_t)(k0 + brow) * Nw + bc16 * 8);
            CP16(st + A_TILE + (uint32_t)brow * SRB3 + (bc16 + 16) * 16,
                 pB + (size_t)(k0 + brow) * Nw + (bc16 + 16) * 8);
            CP_COMMIT();
        }

        uint32_t st = sbase + sidx * STAGE_B;
        const uint32_t aAddr = st + (uint32_t)(wm * 32 + (lane & 15)) * SRA
                             + (lane >> 4) * 16;
        const uint32_t bAddr = st + A_TILE
                             + (uint32_t)(((lane >> 3) & 1) * 8 + (lane & 7)) * SRB3
                             + ((lane >> 4) & 1) * 16 + wn * 128;

        #pragma unroll
        for (int kk = 0; kk < 2; kk++) {
            uint32_t ah[2][4], bb[8][2];
            #pragma unroll
            for (int mt = 0; mt < 2; mt++)
                LDSM4(ah[mt], aAddr + mt * 16 * SRA + kk * 32);
            #pragma unroll
            for (int np = 0; np < 4; np++) {
                uint32_t r[4];
                LDSM4T(r, bAddr + kk * 16 * SRB3 + np * 32);
                bb[2*np][0] = r[0]; bb[2*np][1] = r[1];
                bb[2*np+1][0] = r[2]; bb[2*np+1][1] = r[3];
            }
            #pragma unroll
            for (int mt = 0; mt < 2; mt++)
                #pragma unroll
                for (int nt = 0; nt < 8; nt++)
                    MMAH(A.a[mt][nt], ah[mt], bb[nt]);
        }
        if (++sidx == 3) sidx = 0;
    }
}

// ---- merged QKV projection + fused RoPE: grid (24, 16), 512 threads ----
__global__ __launch_bounds__(512) void gemm_qkv(
    const __half* __restrict__ Ah,
    const __half* __restrict__ WQ, const __half* __restrict__ WK,
    const __half* __restrict__ WV, const int* __restrict__ pos,
    __half* __restrict__ Qh, __half* __restrict__ Kh, __half* __restrict__ Vh)
{
    extern __shared__ char smraw[];
    const uint32_t sbase = smem_to_u32(smraw);
    const int bx = blockIdx.x;
    const int Kd = DD;

    const __half* pB;
    int bn, kind, Nw;   // kind 0=q(rope), 1=k(rope), 2=v(fp16 direct)
    if (bx < 16)      { pB = WQ; bn = bx;      kind = 0; Nw = NH * HD; }
    else if (bx < 20) { pB = WK; bn = bx - 16; kind = 1; Nw = KH * HD; }
    else              { pB = WV; bn = bx - 20; kind = 2; Nw = KH * HD; }
    pB += (size_t)bn * 256;

    AccT A;
    #pragma unroll
    for (int mt = 0; mt < 2; mt++)
        #pragma unroll
        for (int nt = 0; nt < 8; nt++)
            #pragma unroll
            for (int q = 0; q < 4; q++) A.a[mt][nt][q] = 0.f;

    gemm_core(sbase, Ah + (size_t)blockIdx.y * 128 * Kd, pB, Kd, Nw, A);

    const int tid = threadIdx.x;
    const int lane = tid & 31, wid = tid >> 5;
    const int wm = wid >> 2, wn = wid & 3;

    if (kind == 2) {
        const int rb = blockIdx.y * 128 + wm * 32 + (lane >> 2);
        const int cbl = bn * 256 + wn * 64 + (lane & 3) * 2;
        #pragma unroll
        for (int mt = 0; mt < 2; mt++)
            #pragma unroll
            for (int nt = 0; nt < 8; nt++) {
                const int row = rb + mt * 16;
                const int col = cbl + nt * 8;
                *(__half2*)(Vh + (size_t)row * (KH*HD) + col) =
                    __floats2half2_rn(A.a[mt][nt][0], A.a[mt][nt][1]);
                *(__half2*)(Vh + (size_t)(row + 8) * (KH*HD) + col) =
                    __floats2half2_rn(A.a[mt][nt][2], A.a[mt][nt][3]);
            }
        return;
    }

    // ---- fused RoPE: two heads per tile, staged one at a time ----
    float* sm = (float*)smraw;         // [128][130]
    const float scale = (kind == 0) ? SCALE : 1.0f;
    __half* dst = (kind == 0) ? Qh : Kh;
    const int HEADS = (kind == 0) ? NH : KH;
    const int c = tid & 63;
    const int rblk = tid >> 6;         // 0..7
    const float invf = 1.0f / powf(10000.0f, (float)c * (1.0f / 64.0f));

    #pragma unroll
    for (int h2 = 0; h2 < 2; h2++) {
        __syncthreads();               // stage smem free / prev half consumed
        if ((wn >> 1) == h2) {
            const int lc = (wn & 1) * 64;
            #pragma unroll
            for (int mt = 0; mt < 2; mt++)
                #pragma unroll
                for (int nt = 0; nt < 8; nt++) {
                    const int rl = wm * 32 + mt * 16 + (lane >> 2);
                    const int cl = lc + nt * 8 + (lane & 3) * 2;
                    *(float2*)&sm[rl * 130 + cl] =
                        make_float2(A.a[mt][nt][0], A.a[mt][nt][1]);
                    *(float2*)&sm[(rl + 8) * 130 + cl] =
                        make_float2(A.a[mt][nt][2], A.a[mt][nt][3]);
                }
        }
        __syncthreads();
        const int head = bn * 2 + h2;
        #pragma unroll 4
        for (int i = 0; i < 16; i++) {
            const int row = rblk + 8 * i;
            const int t = blockIdx.y * 128 + row;
            float sn, cs;
            sincosf((float)pos[t] * invf, &sn, &cs);
            const float x1 = sm[row * 130 + c];
            const float x2 = sm[row * 130 + c + 64];
            const size_t o = ((size_t)t * HEADS + head) * HD + c;
            dst[o]      = __float2half_rn((x1 * cs - x2 * sn) * scale);
            dst[o + 64] = __float2half_rn((x2 * cs + x1 * sn) * scale);
        }
    }
}

// ---- o-proj: C fp32, grid (16, 16), 512 threads ----
__global__ __launch_bounds__(512) void gemm_o(
    const __half* __restrict__ Ah, const __half* __restrict__ B,
    float* __restrict__ C)
{
    extern __shared__ char smraw[];
    const uint32_t sbase = smem_to_u32(smraw);
    const int Kd = DD, N = DD;

    AccT A;
    #pragma unroll
    for (int mt = 0; mt < 2; mt++)
        #pragma unroll
        for (int nt = 0; nt < 8; nt++)
            #pragma unroll
            for (int q = 0; q < 4; q++) A.a[mt][nt][q] = 0.f;

    gemm_core(sbase, Ah + (size_t)blockIdx.y * 128 * Kd,
              B + (size_t)blockIdx.x * 256, Kd, N, A);

    const int lane = threadIdx.x & 31, wid = threadIdx.x >> 5;
    const int wm = wid >> 2, wn = wid & 3;
    const int rb = blockIdx.y * 128 + wm * 32 + (lane >> 2);
    const int cb = blockIdx.x * 256 + wn * 64 + (lane & 3) * 2;
    #pragma unroll
    for (int mt = 0; mt < 2; mt++)
        #pragma unroll
        for (int nt = 0; nt < 8; nt++) {
            const int row = rb + mt * 16;
            const int col = cb + nt * 8;
            *(float2*)(C + (size_t)row * N + col) =
                make_float2(A.a[mt][nt][0], A.a[mt][nt][1]);
            *(float2*)(C + (size_t)(row + 8) * N + col) =
                make_float2(A.a[mt][nt][2], A.a[mt][nt][3]);
        }
}

// ====================== HMMA flash attention (causal, GQA) ======================
// CTA: 128 q rows x 1 head, 8 warps (16 q rows each). KV tiles of 64.
#define SRH 136
#define SRB 272
#define FL_SMEM ((4 * 64 * SRH) * 2)   // 2 stages of (K,V) = 69632

__global__ __launch_bounds__(256) void flash_h(
    const __half* __restrict__ Qv, const __half* __restrict__ Kv,
    const __half* __restrict__ Vv, __half* __restrict__ Oh)
{
    extern __shared__ char fsm[];
    const uint32_t uSt = smem_to_u32(fsm);

    const int tid = threadIdx.x, lane = tid & 31, wid = tid >> 5;
    const int qi = gridDim.x - 1 - blockIdx.x;     // heavy tiles first
    const int n = blockIdx.y, kvh = n >> 2;
    const int tq0 = qi * 128;
    const int ntiles = 2 * qi + 2;

    const __half* Qg = Qv + ((size_t)tq0 * NH + n) * HD;
    const __half* Kg = Kv + (size_t)kvh * HD;
    const __half* Vg = Vv + (size_t)kvh * HD;

    // ---- stage Q into stage-0 area, read frags ----
    #pragma unroll
    for (int i = 0; i < 8; i++) {
        int c = tid + 256 * i;
        int row = c >> 4, c16 = c & 15;
        CP16(uSt + (uint32_t)row * SRB + c16 * 16,
             Qg + (size_t)row * (NH * HD) + c16 * 8);
    }
    CP_COMMIT();
    CP_WAIT(0);
    __syncthreads();

    uint32_t qh[8][4];
    {
        const uint32_t qa = uSt + (uint32_t)(wid * 16 + (lane & 15)) * SRB
                          + (lane >> 4) * 16;
        #pragma unroll
        for (int dc = 0; dc < 8; dc++)
            LDSM4(qh[dc], qa + dc * 32);
    }
    __syncthreads();   // stage area free for KV

    // paired ldmatrix lane offsets
    const uint32_t kOff = (uint32_t)((lane >> 4) * 8 + (lane & 7)) * SRB
                        + ((lane >> 3) & 1) * 16;
    const uint32_t vOff = (uint32_t)(((lane >> 3) & 1) * 8 + (lane & 7)) * SRB
                        + ((lane >> 4) & 1) * 16;

    float o[16][4];
    #pragma unroll
    for (int i = 0; i < 16; i++)
        #pragma unroll
        for (int j = 0; j < 4; j++) o[i][j] = 0.f;
    float m0 = -1e30f, m1 = -1e30f, l0 = 0.f, l1 = 0.f;

    // preload tile 0
    #pragma unroll
    for (int i = 0; i < 4; i++) {
        int c = tid + 256 * i;
        int row = c >> 4, c16 = c & 15;
        size_t go = (size_t)row * (KH * HD) + c16 * 8;
        CP16(uSt + (uint32_t)row * SRB + c16 * 16, Kg + go);
        CP16(uSt + 64 * SRB + (uint32_t)row * SRB + c16 * 16, Vg + go);
    }
    CP_COMMIT();

    for (int t = 0; t < ntiles; t++) {
        CP_WAIT(0);
        __syncthreads();                 // tile t visible; all done reading other stage

        if (t + 1 < ntiles) {
            uint32_t st = uSt + ((t + 1) & 1) * (2 * 64 * SRB);
            const int s0 = (t + 1) * 64;
            #pragma unroll
            for (int i = 0; i < 4; i++) {
                int c = tid + 256 * i;
                int row = c >> 4, c16 = c & 15;
                size_t go = (size_t)(s0 + row) * (KH * HD) + c16 * 8;
                CP16(st + (uint32_t)row * SRB + c16 * 16, Kg + go);
                CP16(st + 64 * SRB + (uint32_t)row * SRB + c16 * 16, Vg + go);
            }
            CP_COMMIT();
        }

        const uint32_t uK = uSt + (t & 1) * (2 * 64 * SRB);
        const uint32_t uV = uK + 64 * SRB;

        // ---- S = Q K^T ----
        float s[8][4];
        #pragma unroll
        for (int nt = 0; nt < 8; nt++)
            #pragma unroll
            for (int j = 0; j < 4; j++) s[nt][j] = 0.f;

        #pragma unroll
        for (int dc = 0; dc < 8; dc++) {
            #pragma unroll
            for (int ntp = 0; ntp < 4; ntp++) {
                uint32_t r[4];
                LDSM4(r, uK + kOff + (uint32_t)ntp * 16 * SRB + dc * 32);
                uint32_t b0[2] = {r[0], r[1]}, b1[2] = {r[2], r[3]};
                MMAH(s[2*ntp],     qh[dc], b0);
                MMAH(s[2*ntp + 1], qh[dc], b1);
            }
        }

        // ---- causal mask ----
        if (t >= 2 * qi) {
            const int r0 = tq0 + wid * 16 + (lane >> 2);
            const int cB = t * 64 + (lane & 3) * 2;
            #pragma unroll
            for (int nt = 0; nt < 8; nt++) {
                int c0 = cB + nt * 8;
                if (c0     > r0)     s[nt][0] = -1e30f;
                if (c0 + 1 > r0)     s[nt][1] = -1e30f;
                if (c0     > r0 + 8) s[nt][2] = -1e30f;
                if (c0 + 1 > r0 + 8) s[nt][3] = -1e30f;
            }
        }

        // ---- online softmax ----
        float mr0 = -1e30f, mr1 = -1e30f;
        #pragma unroll
        for (int nt = 0; nt < 8; nt++) {
            mr0 = fmaxf(mr0, fmaxf(s[nt][0], s[nt][1]));
            mr1 = fmaxf(mr1, fmaxf(s[nt][2], s[nt][3]));
        }
        mr0 = fmaxf(mr0, __shfl_xor_sync(0xffffffffu, mr0, 1));
        mr0 = fmaxf(mr0, __shfl_xor_sync(0xffffffffu, mr0, 2));
        mr1 = fmaxf(mr1, __shfl_xor_sync(0xffffffffu, mr1, 1));
        mr1 = fmaxf(mr1, __shfl_xor_sync(0xffffffffu, mr1, 2));

        const float mn0 = fmaxf(m0, mr0), mn1 = fmaxf(m1, mr1);
        const float a0 = __expf(m0 - mn0), a1 = __expf(m1 - mn1);
        m0 = mn0; m1 = mn1;

        float ls0 = 0.f, ls1 = 0.f;
        #pragma unroll
        for (int nt = 0; nt < 8; nt++) {
            s[nt][0] = __expf(s[nt][0] - m0); ls0 += s[nt][0];
            s[nt][1] = __expf(s[nt][1] - m0); ls0 += s[nt][1];
            s[nt][2] = __expf(s[nt][2] - m1); ls1 += s[nt][2];
            s[nt][3] = __expf(s[nt][3] - m1); ls1 += s[nt][3];
        }
        ls0 += __shfl_xor_sync(0xffffffffu, ls0, 1);
        ls0 += __shfl_xor_sync(0xffffffffu, ls0, 2);
        ls1 += __shfl_xor_sync(0xffffffffu, ls1, 1);
        ls1 += __shfl_xor_sync(0xffffffffu, ls1, 2);
        l0 = l0 * a0 + ls0;
        l1 = l1 * a1 + ls1;

        #pragma unroll
        for (int i = 0; i < 16; i++) {
            o[i][0] *= a0; o[i][1] *= a0; o[i][2] *= a1; o[i][3] *= a1;
        }

        // ---- P fragments (single fp16) ----
        uint32_t phi[4][4];
        #pragma unroll
        for (int kc = 0; kc < 4; kc++) {
            #pragma unroll
            for (int q = 0; q < 4; q++) {
                int nt = 2 * kc + (q >> 1);
                __half2 h = __floats2half2_rn(s[nt][(q & 1) * 2],
                                              s[nt][(q & 1) * 2 + 1]);
                phi[kc][q] = *(uint32_t*)&h;
            }
        }

        // ---- O += P V ----
        #pragma unroll
        for (int np = 0; np < 8; np++) {
            #pragma unroll
            for (int kc = 0; kc < 4; kc++) {
                uint32_t r[4];
                LDSM4T(r, uV + vOff + (uint32_t)kc * 16 * SRB + np * 32);
                uint32_t b0[2] = {r[0], r[1]}, b1[2] = {r[2], r[3]};
                MMAH(o[2*np],     phi[kc], b0);
                MMAH(o[2*np + 1], phi[kc], b1);
            }
        }
    }

    // ---- epilogue: O / l, write single fp16 ----
    const float i0 = 1.f / l0, i1 = 1.f / l1;
    const int r0 = tq0 + wid * 16 + (lane >> 2);
    const int cofs = (lane & 3) * 2;
    #pragma unroll
    for (int nt2 = 0; nt2 < 16; nt2++) {
        float v0 = o[nt2][0] * i0, v1 = o[nt2][1] * i0;
        float v2 = o[nt2][2] * i1, v3 = o[nt2][3] * i1;
        size_t p0 = ((size_t)r0 * NH + n) * HD + nt2 * 8 + cofs;
        size_t p1 = ((size_t)(r0 + 8) * NH + n) * HD + nt2 * 8 + cofs;
        *(__half2*)(Oh + p0) = __floats2half2_rn(v0, v1);
        *(__half2*)(Oh + p1) = __floats2half2_rn(v2, v3);
    }
}

// ====================== launch ======================
extern "C" void kernel_launch(void* const* d_in, const int* in_sizes, int n_in,
                              void* d_out, int out_size)
{
    const float* x   = (const float*)d_in[0];
    const int*   pos = (const int*)  d_in[1];
    const float* w_q = (const float*)d_in[2];
    const float* w_k = (const float*)d_in[3];
    const float* w_v = (const float*)d_in[4];
    const float* w_o = (const float*)d_in[5];
    float* out = (float*)d_out;

    __half *xh, *aoh, *wq16, *wk16, *wv16, *wo16, *qh, *kh, *vh;
    cudaGetSymbolAddress((void**)&xh,   g_xh);
    cudaGetSymbolAddress((void**)&aoh,  g_aoh);
    cudaGetSymbolAddress((void**)&wq16, g_wq16); cudaGetSymbolAddress((void**)&wk16, g_wk16);
    cudaGetSymbolAddress((void**)&wv16, g_wv16); cudaGetSymbolAddress((void**)&wo16, g_wo16);
    cudaGetSymbolAddress((void**)&qh,   g_qh);
    cudaGetSymbolAddress((void**)&kh,   g_kh);   cudaGetSymbolAddress((void**)&vh,   g_vh);

    cudaFuncSetAttribute(gemm_qkv, cudaFuncAttributeMaxDynamicSharedMemorySize, GEMM_SMEM);
    cudaFuncSetAttribute(gemm_o,   cudaFuncAttributeMaxDynamicSharedMemorySize, GEMM_SMEM);
    cudaFuncSetAttribute(flash_h,  cudaFuncAttributeMaxDynamicSharedMemorySize, FL_SMEM);

    // fused fp16 conversions (x + all weights)
    conv_all<<<(F4_TOT + 255)/256, 256>>>(x, w_q, w_k, w_v, w_o,
                                          xh, wq16, wk16, wv16, wo16);

    // merged QKV projection + fused RoPE (128x256 tiles)
    gemm_qkv<<<dim3(24, 16), 512, GEMM_SMEM>>>(xh, wq16, wk16, wv16, pos, qh, kh, vh);

    // causal GQA flash attention (HMMA, all single fp16)
    flash_h<<<dim3(TT/128, NH), 256, FL_SMEM>>>(qh, kh, vh, aoh);

    // output projection (128x256 tiles)
    gemm_o<<<dim3(16, 16), 512, GEMM_SMEM>>>(aoh, wo16, out);
}

// round 14
// speedup vs baseline: 1.0276x; 1.0276x over previous
#include <cuda_runtime.h>
#include <cuda_fp16.h>
#include <cstdint>
#include <math.h>

// Problem constants
#define TT 2048
#define DD 4096
#define NH 32
#define KH 8
#define HD 128
#define SCALE 0.08838834764831843f   // 1/sqrt(128)

// ====================== PTX helpers (base sm_103-legal only) ======================
__device__ __forceinline__ uint32_t smem_to_u32(const void* p) {
    uint32_t a;
    asm("{ .reg .u64 t; cvta.to.shared.u64 t, %1; cvt.u32.u64 %0, t; }" : "=r"(a) : "l"(p));
    return a;
}
#define CP16(sa, ga) \
    asm volatile("cp.async.cg.shared.global [%0], [%1], 16;" :: "r"(sa), "l"(ga) : "memory")
#define CP_COMMIT() asm volatile("cp.async.commit_group;" ::: "memory")
#define CP_WAIT(n)  asm volatile("cp.async.wait_group %0;" :: "n"(n) : "memory")
#define LDSM4(r, a) \
    asm volatile("ldmatrix.sync.aligned.m8n8.x4.shared.b16 {%0,%1,%2,%3}, [%4];" \
        : "=r"((r)[0]), "=r"((r)[1]), "=r"((r)[2]), "=r"((r)[3]) : "r"(a))
#define LDSM4T(r, a) \
    asm volatile("ldmatrix.sync.aligned.m8n8.x4.trans.shared.b16 {%0,%1,%2,%3}, [%4];" \
        : "=r"((r)[0]), "=r"((r)[1]), "=r"((r)[2]), "=r"((r)[3]) : "r"(a))
#define MMAH(d, a, b) \
    asm volatile("mma.sync.aligned.m16n8k16.row.col.f32.f16.f16.f32 " \
        "{%0,%1,%2,%3}, {%4,%5,%6,%7}, {%8,%9}, {%0,%1,%2,%3};" \
        : "+f"((d)[0]), "+f"((d)[1]), "+f"((d)[2]), "+f"((d)[3]) \
        : "r"((a)[0]), "r"((a)[1]), "r"((a)[2]), "r"((a)[3]), "r"((b)[0]), "r"((b)[1]))

// ====================== device scratch ======================
__device__ __half g_xh  [TT * DD];
__device__ __half g_aoh [TT * DD];
__device__ __half g_wq16[DD * DD];       // fp16 copy, natural [K,N] layout
__device__ __half g_wk16[DD * KH*HD];
__device__ __half g_wv16[DD * KH*HD];
__device__ __half g_wo16[DD * DD];
__device__ __half g_qh  [TT * NH * HD];
__device__ __half g_kh  [TT * KH * HD];
__device__ __half g_vh  [TT * KH * HD];

// ====================== fused fp32 -> fp16 convert (all 5 tensors) ============
#define F4_X  2097152
#define F4_WQ 4194304
#define F4_WK 1048576
#define F4_WV 1048576
#define F4_WO 4194304
#define F4_TOT (F4_X + F4_WQ + F4_WK + F4_WV + F4_WO)   // 12582912

__global__ void conv_all(
    const float* __restrict__ x,  const float* __restrict__ wq,
    const float* __restrict__ wk, const float* __restrict__ wv,
    const float* __restrict__ wo,
    __half* __restrict__ xh, __half* __restrict__ wqh, __half* __restrict__ wkh,
    __half* __restrict__ wvh, __half* __restrict__ woh)
{
    long long i = (long long)blockIdx.x * 256 + threadIdx.x;
    if (i >= F4_TOT) return;
    const float* s; __half* d;
    if (i < F4_X)                         { s = x;  d = xh; }
    else if (i < F4_X + F4_WQ)            { s = wq; d = wqh; i -= F4_X; }
    else if (i < F4_X + F4_WQ + F4_WK)    { s = wk; d = wkh; i -= F4_X + F4_WQ; }
    else if (i < F4_X + F4_WQ + 2*F4_WK)  { s = wv; d = wvh; i -= F4_X + F4_WQ + F4_WK; }
    else                                  { s = wo; d = woh; i -= F4_X + F4_WQ + 2*F4_WK; }
    float4 f = ((const float4*)s)[i];
    __align__(8) __half h[4] = {__float2half_rn(f.x), __float2half_rn(f.y),
                                __float2half_rn(f.z), __float2half_rn(f.w)};
    *(uint2*)(d + 4 * (size_t)i) = *(uint2*)h;
}

// ====================== mma.sync GEMM core ======================
// 128x128 CTA tile, BK=32, 256 threads, 8 warps (2x4), warp tile 64x32, 3-stage.
// A smem [M,K] (non-trans frags).  B smem [K,N] (trans frags).
#define SRA 80                         // A row stride bytes (32 halves + pad)
#define SRB2 272                       // B row stride bytes (128 halves + pad)
#define A_TILE (128 * SRA)             // 10240
#define B_TILE (32 * SRB2)             // 8704
#define STAGE_B (A_TILE + B_TILE)      // 18944
#define GEMM_SMEM (3 * STAGE_B)        // 56832
#define QKV_SMEM 66560                 // max(GEMM_SMEM, 128*130*4 epilogue stage)

struct AccT { float a[4][4][4]; };

__device__ __forceinline__ void gemm_core(
    uint32_t sbase, const __half* pA, const __half* pB, int Kd, int Nw, AccT& A)
{
    const int tid = threadIdx.x, lane = tid & 31, wid = tid >> 5;
    const int wm = wid >> 2, wn = wid & 3;
    const int arow = tid >> 2;             // 0..63 (+64)
    const uint32_t aso = (tid & 3) * 16;
    const int acol = (tid & 3) * 8;
    const int brow = tid >> 4;             // 0..15 (+16)
    const int bc16 = tid & 15;

    const int nst = Kd >> 5;

    #pragma unroll
    for (int ps = 0; ps < 2; ps++) {       // prologue stages 0,1
        const int k0 = ps << 5;
        uint32_t st = sbase + ps * STAGE_B;
        #pragma unroll
        for (int i = 0; i < 2; i++) {
            int row = arow + 64 * i;
            CP16(st + (uint32_t)row * SRA + aso, pA + (size_t)row * Kd + k0 + acol);
        }
        #pragma unroll
        for (int i = 0; i < 2; i++) {
            int row = brow + 16 * i;
            CP16(st + A_TILE + (uint32_t)row * SRB2 + bc16 * 16,
                 pB + (size_t)(k0 + row) * Nw + bc16 * 8);
        }
        CP_COMMIT();
    }

    int sidx = 0;
    for (int s = 0; s < nst; s++) {
        if (s + 1 < nst) { CP_WAIT(1); } else { CP_WAIT(0); }
        __syncthreads();                   // single barrier per stage

        if (s + 2 < nst) {
            const int k0 = (s + 2) << 5;
            int lidx = sidx - 1; if (lidx < 0) lidx += 3;
            uint32_t st = sbase + lidx * STAGE_B;
            #pragma unroll
            for (int i = 0; i < 2; i++) {
                int row = arow + 64 * i;
                CP16(st + (uint32_t)row * SRA + aso, pA + (size_t)row * Kd + k0 + acol);
            }
            #pragma unroll
            for (int i = 0; i < 2; i++) {
                int row = brow + 16 * i;
                CP16(st + A_TILE + (uint32_t)row * SRB2 + bc16 * 16,
                     pB + (size_t)(k0 + row) * Nw + bc16 * 8);
            }
            CP_COMMIT();
        }

        uint32_t st = sbase + sidx * STAGE_B;
        const uint32_t aAddr = st + (uint32_t)(wm * 64 + (lane & 15)) * SRA
                             + (lane >> 4) * 16;
        const uint32_t bAddr = st + A_TILE
                             + (uint32_t)(((lane >> 3) & 1) * 8 + (lane & 7)) * SRB2
                             + ((lane >> 4) & 1) * 16 + wn * 64;

        #pragma unroll
        for (int kk = 0; kk < 2; kk++) {
            uint32_t ah[4][4], bb[4][2];
            #pragma unroll
            for (int mt = 0; mt < 4; mt++)
                LDSM4(ah[mt], aAddr + mt * 16 * SRA + kk * 32);
            #pragma unroll
            for (int np = 0; np < 2; np++) {
                uint32_t r[4];
                LDSM4T(r, bAddr + kk * 16 * SRB2 + np * 32);
                bb[2*np][0] = r[0]; bb[2*np][1] = r[1];
                bb[2*np+1][0] = r[2]; bb[2*np+1][1] = r[3];
            }
            #pragma unroll
            for (int mt = 0; mt < 4; mt++)
                #pragma unroll
                for (int nt = 0; nt < 4; nt++)
                    MMAH(A.a[mt][nt], ah[mt], bb[nt]);
        }
        if (++sidx == 3) sidx = 0;
    }
}

// ---- merged QKV projection + fused RoPE: grid (48, 16) ----
__global__ __launch_bounds__(256) void gemm_qkv(
    const __half* __restrict__ Ah,
    const __half* __restrict__ WQ, const __half* __restrict__ WK,
    const __half* __restrict__ WV, const int* __restrict__ pos,
    __half* __restrict__ Qh, __half* __restrict__ Kh, __half* __restrict__ Vh)
{
    extern __shared__ char smraw[];
    const uint32_t sbase = smem_to_u32(smraw);
    const int bx = blockIdx.x;
    const int Kd = DD;

    const __half* pB;
    int bn, kind, Nw;   // kind 0=q(rope), 1=k(rope), 2=v(fp16 direct)
    if (bx < 32)      { pB = WQ; bn = bx;      kind = 0; Nw = NH * HD; }
    else if (bx < 40) { pB = WK; bn = bx - 32; kind = 1; Nw = KH * HD; }
    else              { pB = WV; bn = bx - 40; kind = 2; Nw = KH * HD; }
    pB += (size_t)bn * 128;

    AccT A;
    #pragma unroll
    for (int mt = 0; mt < 4; mt++)
        #pragma unroll
        for (int nt = 0; nt < 4; nt++)
            #pragma unroll
            for (int q = 0; q < 4; q++) A.a[mt][nt][q] = 0.f;

    gemm_core(sbase, Ah + (size_t)blockIdx.y * 128 * Kd, pB, Kd, Nw, A);

    const int tid = threadIdx.x;
    const int lane = tid & 31, wid = tid >> 5;
    const int wm = wid >> 2, wn = wid & 3;

    if (kind == 2) {
        const int rb = blockIdx.y * 128 + wm * 64 + (lane >> 2);
        const int cbl = bn * 128 + wn * 32 + (lane & 3) * 2;
        #pragma unroll
        for (int mt = 0; mt < 4; mt++)
            #pragma unroll
            for (int nt = 0; nt < 4; nt++) {
                const int row = rb + mt * 16;
                const int col = cbl + nt * 8;
                *(__half2*)(Vh + (size_t)row * (KH*HD) + col) =
                    __floats2half2_rn(A.a[mt][nt][0], A.a[mt][nt][1]);
                *(__half2*)(Vh + (size_t)(row + 8) * (KH*HD) + col) =
                    __floats2half2_rn(A.a[mt][nt][2], A.a[mt][nt][3]);
            }
        return;
    }

    // ---- fused RoPE: stage fp32 tile in smem, rotate pairs (c, c+64) ----
    __syncthreads();                   // all warps done reading stage smem
    float* sm = (float*)smraw;         // [128][130]
    #pragma unroll
    for (int mt = 0; mt < 4; mt++)
        #pragma unroll
        for (int nt = 0; nt < 4; nt++) {
            const int rl = wm * 64 + mt * 16 + (lane >> 2);
            const int cl = wn * 32 + (lane & 3) * 2 + nt * 8;
            *(float2*)&sm[rl * 130 + cl] = make_float2(A.a[mt][nt][0], A.a[mt][nt][1]);
            *(float2*)&sm[(rl + 8) * 130 + cl] = make_float2(A.a[mt][nt][2], A.a[mt][nt][3]);
        }
    __syncthreads();

    const float scale = (kind == 0) ? SCALE : 1.0f;
    __half* dst = (kind == 0) ? Qh : Kh;
    const int HEADS = (kind == 0) ? NH : KH;
    const int c = tid & 63;
    const int rbase = tid >> 6;        // 0..3
    const float e = (float)c * (1.0f / 64.0f);
    const float invf = 1.0f / powf(10000.0f, e);

    #pragma unroll 4
    for (int i = 0; i < 32; i++) {
        const int row = i * 4 + rbase;
        const int t = blockIdx.y * 128 + row;
        float sn, cs;
        sincosf((float)pos[t] * invf, &sn, &cs);
        const float x1 = sm[row * 130 + c];
        const float x2 = sm[row * 130 + c + 64];
        const size_t o = ((size_t)t * HEADS + bn) * HD + c;
        dst[o]      = __float2half_rn((x1 * cs - x2 * sn) * scale);
        dst[o + 64] = __float2half_rn((x2 * cs + x1 * sn) * scale);
    }
}

// ---- o-proj: C fp32, grid (32, 16) ----
__global__ __launch_bounds__(256) void gemm_o(
    const __half* __restrict__ Ah, const __half* __restrict__ B,
    float* __restrict__ C)
{
    extern __shared__ char smraw[];
    const uint32_t sbase = smem_to_u32(smraw);
    const int Kd = DD, N = DD;

    AccT A;
    #pragma unroll
    for (int mt = 0; mt < 4; mt++)
        #pragma unroll
        for (int nt = 0; nt < 4; nt++)
            #pragma unroll
            for (int q = 0; q < 4; q++) A.a[mt][nt][q] = 0.f;

    gemm_core(sbase, Ah + (size_t)blockIdx.y * 128 * Kd,
              B + (size_t)blockIdx.x * 128, Kd, N, A);

    const int lane = threadIdx.x & 31, wid = threadIdx.x >> 5;
    const int wm = wid >> 2, wn = wid & 3;
    const int rb = blockIdx.y * 128 + wm * 64 + (lane >> 2);
    const int cb = blockIdx.x * 128 + wn * 32 + (lane & 3) * 2;
    #pragma unroll
    for (int mt = 0; mt < 4; mt++)
        #pragma unroll
        for (int nt = 0; nt < 4; nt++) {
            const int row = rb + mt * 16;
            const int col = cb + nt * 8;
            *(float2*)(C + (size_t)row * N + col) =
                make_float2(A.a[mt][nt][0], A.a[mt][nt][1]);
            *(float2*)(C + (size_t)(row + 8) * N + col) =
                make_float2(A.a[mt][nt][2], A.a[mt][nt][3]);
        }
}

// ====================== HMMA flash attention (causal, GQA) ======================
// CTA: 128 q rows x 1 head, 8 warps (16 q rows each). KV tiles of 64, 3 stages.
#define SRB 272
#define FL_STAGE (2 * 64 * SRB)        // K + V per tile = 34816
#define FL_SMEM (3 * FL_STAGE)         // 104448

__global__ __launch_bounds__(256) void flash_h(
    const __half* __restrict__ Qv, const __half* __restrict__ Kv,
    const __half* __restrict__ Vv, __half* __restrict__ Oh)
{
    extern __shared__ char fsm[];
    const uint32_t uSt = smem_to_u32(fsm);

    const int tid = threadIdx.x, lane = tid & 31, wid = tid >> 5;
    const int qi = gridDim.x - 1 - blockIdx.x;     // heavy tiles first
    const int n = blockIdx.y, kvh = n >> 2;
    const int tq0 = qi * 128;
    const int ntiles = 2 * qi + 2;

    const __half* Qg = Qv + ((size_t)tq0 * NH + n) * HD;
    const __half* Kg = Kv + (size_t)kvh * HD;
    const __half* Vg = Vv + (size_t)kvh * HD;

    // ---- stage Q into stage-0 area, read frags ----
    #pragma unroll
    for (int i = 0; i < 8; i++) {
        int c = tid + 256 * i;
        int row = c >> 4, c16 = c & 15;
        CP16(uSt + (uint32_t)row * SRB + c16 * 16,
             Qg + (size_t)row * (NH * HD) + c16 * 8);
    }
    CP_COMMIT();
    CP_WAIT(0);
    __syncthreads();

    uint32_t qh[8][4];
    {
        const uint32_t qa = uSt + (uint32_t)(wid * 16 + (lane & 15)) * SRB
                          + (lane >> 4) * 16;
        #pragma unroll
        for (int dc = 0; dc < 8; dc++)
            LDSM4(qh[dc], qa + dc * 32);
    }
    __syncthreads();   // stage area free for KV

    // paired ldmatrix lane offsets
    const uint32_t kOff = (uint32_t)((lane >> 4) * 8 + (lane & 7)) * SRB
                        + ((lane >> 3) & 1) * 16;
    const uint32_t vOff = (uint32_t)(((lane >> 3) & 1) * 8 + (lane & 7)) * SRB
                        + ((lane >> 4) & 1) * 16;

    float o[16][4];
    #pragma unroll
    for (int i = 0; i < 16; i++)
        #pragma unroll
        for (int j = 0; j < 4; j++) o[i][j] = 0.f;
    float m0 = -1e30f, m1 = -1e30f, l0 = 0.f, l1 = 0.f;

    // preload tiles 0 and 1 (ntiles >= 2 always)
    #pragma unroll
    for (int ps = 0; ps < 2; ps++) {
        uint32_t st = uSt + ps * FL_STAGE;
        const int s0 = ps * 64;
        #pragma unroll
        for (int i = 0; i < 4; i++) {
            int c = tid + 256 * i;
            int row = c >> 4, c16 = c & 15;
            size_t go = (size_t)(s0 + row) * (KH * HD) + c16 * 8;
            CP16(st + (uint32_t)row * SRB + c16 * 16, Kg + go);
            CP16(st + 64 * SRB + (uint32_t)row * SRB + c16 * 16, Vg + go);
        }
        CP_COMMIT();
    }

    int sidx = 0;
    for (int t = 0; t < ntiles; t++) {
        if (t + 1 < ntiles) { CP_WAIT(1); } else { CP_WAIT(0); }
        __syncthreads();                 // tile t visible; stage (t+2)%3 free

        if (t + 2 < ntiles) {
            int lidx = sidx - 1; if (lidx < 0) lidx += 3;
            uint32_t st = uSt + lidx * FL_STAGE;
            const int s0 = (t + 2) * 64;
            #pragma unroll
            for (int i = 0; i < 4; i++) {
                int c = tid + 256 * i;
                int row = c >> 4, c16 = c & 15;
                size_t go = (size_t)(s0 + row) * (KH * HD) + c16 * 8;
                CP16(st + (uint32_t)row * SRB + c16 * 16, Kg + go);
                CP16(st + 64 * SRB + (uint32_t)row * SRB + c16 * 16, Vg + go);
            }
            CP_COMMIT();
        }

        const uint32_t uK = uSt + sidx * FL_STAGE;
        const uint32_t uV = uK + 64 * SRB;

        // ---- S = Q K^T ----
        float s[8][4];
        #pragma unroll
        for (int nt = 0; nt < 8; nt++)
            #pragma unroll
            for (int j = 0; j < 4; j++) s[nt][j] = 0.f;

        #pragma unroll
        for (int dc = 0; dc < 8; dc++) {
            #pragma unroll
            for (int ntp = 0; ntp < 4; ntp++) {
                uint32_t r[4];
                LDSM4(r, uK + kOff + (uint32_t)ntp * 16 * SRB + dc * 32);
                uint32_t b0[2] = {r[0], r[1]}, b1[2] = {r[2], r[3]};
                MMAH(s[2*ntp],     qh[dc], b0);
                MMAH(s[2*ntp + 1], qh[dc], b1);
            }
        }

        // ---- causal mask ----
        if (t >= 2 * qi) {
            const int r0 = tq0 + wid * 16 + (lane >> 2);
            const int cB = t * 64 + (lane & 3) * 2;
            #pragma unroll
            for (int nt = 0; nt < 8; nt++) {
                int c0 = cB + nt * 8;
                if (c0     > r0)     s[nt][0] = -1e30f;
                if (c0 + 1 > r0)     s[nt][1] = -1e30f;
                if (c0     > r0 + 8) s[nt][2] = -1e30f;
                if (c0 + 1 > r0 + 8) s[nt][3] = -1e30f;
            }
        }

        // ---- online softmax ----
        float mr0 = -1e30f, mr1 = -1e30f;
        #pragma unroll
        for (int nt = 0; nt < 8; nt++) {
            mr0 = fmaxf(mr0, fmaxf(s[nt][0], s[nt][1]));
            mr1 = fmaxf(mr1, fmaxf(s[nt][2], s[nt][3]));
        }
        mr0 = fmaxf(mr0, __shfl_xor_sync(0xffffffffu, mr0, 1));
        mr0 = fmaxf(mr0, __shfl_xor_sync(0xffffffffu, mr0, 2));
        mr1 = fmaxf(mr1, __shfl_xor_sync(0xffffffffu, mr1, 1));
        mr1 = fmaxf(mr1, __shfl_xor_sync(0xffffffffu, mr1, 2));

        const float mn0 = fmaxf(m0, mr0), mn1 = fmaxf(m1, mr1);
        const float a0 = __expf(m0 - mn0), a1 = __expf(m1 - mn1);
        m0 = mn0; m1 = mn1;

        float ls0 = 0.f, ls1 = 0.f;
        #pragma unroll
        for (int nt = 0; nt < 8; nt++) {
            s[nt][0] = __expf(s[nt][0] - m0); ls0 += s[nt][0];
            s[nt][1] = __expf(s[nt][1] - m0); ls0 += s[nt][1];
            s[nt][2] = __expf(s[nt][2] - m1); ls1 += s[nt][2];
            s[nt][3] = __expf(s[nt][3] - m1); ls1 += s[nt][3];
        }
        ls0 += __shfl_xor_sync(0xffffffffu, ls0, 1);
        ls0 += __shfl_xor_sync(0xffffffffu, ls0, 2);
        ls1 += __shfl_xor_sync(0xffffffffu, ls1, 1);
        ls1 += __shfl_xor_sync(0xffffffffu, ls1, 2);
        l0 = l0 * a0 + ls0;
        l1 = l1 * a1 + ls1;

        #pragma unroll
        for (int i = 0; i < 16; i++) {
            o[i][0] *= a0; o[i][1] *= a0; o[i][2] *= a1; o[i][3] *= a1;
        }

        // ---- P fragments (single fp16) ----
        uint32_t phi[4][4];
        #pragma unroll
        for (int kc = 0; kc < 4; kc++) {
            #pragma unroll
            for (int q = 0; q < 4; q++) {
                int nt = 2 * kc + (q >> 1);
                __half2 h = __floats2half2_rn(s[nt][(q & 1) * 2],
                                              s[nt][(q & 1) * 2 + 1]);
                phi[kc][q] = *(uint32_t*)&h;
            }
        }

        // ---- O += P V ----
        #pragma unroll
        for (int np = 0; np < 8; np++) {
            #pragma unroll
            for (int kc = 0; kc < 4; kc++) {
                uint32_t r[4];
                LDSM4T(r, uV + vOff + (uint32_t)kc * 16 * SRB + np * 32);
                uint32_t b0[2] = {r[0], r[1]}, b1[2] = {r[2], r[3]};
                MMAH(o[2*np],     phi[kc], b0);
                MMAH(o[2*np + 1], phi[kc], b1);
            }
        }
        if (++sidx == 3) sidx = 0;
    }

    // ---- epilogue: O / l, write single fp16 ----
    const float i0 = 1.f / l0, i1 = 1.f / l1;
    const int r0 = tq0 + wid * 16 + (lane >> 2);
    const int cofs = (lane & 3) * 2;
    #pragma unroll
    for (int nt2 = 0; nt2 < 16; nt2++) {
        float v0 = o[nt2][0] * i0, v1 = o[nt2][1] * i0;
        float v2 = o[nt2][2] * i1, v3 = o[nt2][3] * i1;
        size_t p0 = ((size_t)r0 * NH + n) * HD + nt2 * 8 + cofs;
        size_t p1 = ((size_t)(r0 + 8) * NH + n) * HD + nt2 * 8 + cofs;
        *(__half2*)(Oh + p0) = __floats2half2_rn(v0, v1);
        *(__half2*)(Oh + p1) = __floats2half2_rn(v2, v3);
    }
}

// ====================== launch ======================
extern "C" void kernel_launch(void* const* d_in, const int* in_sizes, int n_in,
                              void* d_out, int out_size)
{
    const float* x   = (const float*)d_in[0];
    const int*   pos = (const int*)  d_in[1];
    const float* w_q = (const float*)d_in[2];
    const float* w_k = (const float*)d_in[3];
    const float* w_v = (const float*)d_in[4];
    const float* w_o = (const float*)d_in[5];
    float* out = (float*)d_out;

    __half *xh, *aoh, *wq16, *wk16, *wv16, *wo16, *qh, *kh, *vh;
    cudaGetSymbolAddress((void**)&xh,   g_xh);
    cudaGetSymbolAddress((void**)&aoh,  g_aoh);
    cudaGetSymbolAddress((void**)&wq16, g_wq16); cudaGetSymbolAddress((void**)&wk16, g_wk16);
    cudaGetSymbolAddress((void**)&wv16, g_wv16); cudaGetSymbolAddress((void**)&wo16, g_wo16);
    cudaGetSymbolAddress((void**)&qh,   g_qh);
    cudaGetSymbolAddress((void**)&kh,   g_kh);   cudaGetSymbolAddress((void**)&vh,   g_vh);

    cudaFuncSetAttribute(gemm_qkv, cudaFuncAttributeMaxDynamicSharedMemorySize, QKV_SMEM);
    cudaFuncSetAttribute(gemm_o,   cudaFuncAttributeMaxDynamicSharedMemorySize, GEMM_SMEM);
    cudaFuncSetAttribute(flash_h,  cudaFuncAttributeMaxDynamicSharedMemorySize, FL_SMEM);

    // fused fp16 conversions (x + all weights)
    conv_all<<<(F4_TOT + 255)/256, 256>>>(x, w_q, w_k, w_v, w_o,
                                          xh, wq16, wk16, wv16, wo16);

    // merged QKV projection + fused RoPE (128x128 tiles, 2 CTAs/SM)
    gemm_qkv<<<dim3(48, 16), 256, QKV_SMEM>>>(xh, wq16, wk16, wv16, pos, qh, kh, vh);

    // causal GQA flash attention (HMMA, 3-stage KV pipeline)
    flash_h<<<dim3(TT/128, NH), 256, FL_SMEM>>>(qh, kh, vh, aoh);

    // output projection (128x128 tiles, 2 CTAs/SM)
    gemm_o<<<dim3(32, 16), 256, GEMM_SMEM>>>(aoh, wo16, out);
}

// round 15
// speedup vs baseline: 1.0726x; 1.0438x over previous
#include <cuda_runtime.h>
#include <cuda_fp16.h>
#include <cstdint>
#include <math.h>

// Problem constants
#define TT 2048
#define DD 4096
#define NH 32
#define KH 8
#define HD 128
#define SCALE 0.08838834764831843f   // 1/sqrt(128)

// ====================== PTX helpers (base sm_103-legal only) ======================
__device__ __forceinline__ uint32_t smem_to_u32(const void* p) {
    uint32_t a;
    asm("{ .reg .u64 t; cvta.to.shared.u64 t, %1; cvt.u32.u64 %0, t; }" : "=r"(a) : "l"(p));
    return a;
}
#define CP16(sa, ga) \
    asm volatile("cp.async.cg.shared.global [%0], [%1], 16;" :: "r"(sa), "l"(ga) : "memory")
#define CP_COMMIT() asm volatile("cp.async.commit_group;" ::: "memory")
#define CP_WAIT(n)  asm volatile("cp.async.wait_group %0;" :: "n"(n) : "memory")
#define LDSM4(r, a) \
    asm volatile("ldmatrix.sync.aligned.m8n8.x4.shared.b16 {%0,%1,%2,%3}, [%4];" \
        : "=r"((r)[0]), "=r"((r)[1]), "=r"((r)[2]), "=r"((r)[3]) : "r"(a))
#define LDSM4T(r, a) \
    asm volatile("ldmatrix.sync.aligned.m8n8.x4.trans.shared.b16 {%0,%1,%2,%3}, [%4];" \
        : "=r"((r)[0]), "=r"((r)[1]), "=r"((r)[2]), "=r"((r)[3]) : "r"(a))
#define MMAH(d, a, b) \
    asm volatile("mma.sync.aligned.m16n8k16.row.col.f32.f16.f16.f32 " \
        "{%0,%1,%2,%3}, {%4,%5,%6,%7}, {%8,%9}, {%0,%1,%2,%3};" \
        : "+f"((d)[0]), "+f"((d)[1]), "+f"((d)[2]), "+f"((d)[3]) \
        : "r"((a)[0]), "r"((a)[1]), "r"((a)[2]), "r"((a)[3]), "r"((b)[0]), "r"((b)[1]))

// ====================== device scratch ======================
__device__ __half g_xh  [TT * DD];
__device__ __half g_aoh [TT * DD];
__device__ __half g_wq16[DD * DD];       // fp16 copy, natural [K,N] layout
__device__ __half g_wk16[DD * KH*HD];
__device__ __half g_wv16[DD * KH*HD];
__device__ __half g_wo16[DD * DD];
__device__ __half g_qh  [TT * NH * HD];
__device__ __half g_kh  [TT * KH * HD];
__device__ __half g_vh  [TT * KH * HD];

// ====================== fused fp32 -> fp16 convert (all 5 tensors) ============
#define F4_X  2097152
#define F4_WQ 4194304
#define F4_WK 1048576
#define F4_WV 1048576
#define F4_WO 4194304
#define F4_TOT (F4_X + F4_WQ + F4_WK + F4_WV + F4_WO)   // 12582912

__global__ void conv_all(
    const float* __restrict__ x,  const float* __restrict__ wq,
    const float* __restrict__ wk, const float* __restrict__ wv,
    const float* __restrict__ wo,
    __half* __restrict__ xh, __half* __restrict__ wqh, __half* __restrict__ wkh,
    __half* __restrict__ wvh, __half* __restrict__ woh)
{
    long long i = (long long)blockIdx.x * 256 + threadIdx.x;
    if (i >= F4_TOT) return;
    const float* s; __half* d;
    if (i < F4_X)                         { s = x;  d = xh; }
    else if (i < F4_X + F4_WQ)            { s = wq; d = wqh; i -= F4_X; }
    else if (i < F4_X + F4_WQ + F4_WK)    { s = wk; d = wkh; i -= F4_X + F4_WQ; }
    else if (i < F4_X + F4_WQ + 2*F4_WK)  { s = wv; d = wvh; i -= F4_X + F4_WQ + F4_WK; }
    else                                  { s = wo; d = woh; i -= F4_X + F4_WQ + 2*F4_WK; }
    float4 f = ((const float4*)s)[i];
    __align__(8) __half h[4] = {__float2half_rn(f.x), __float2half_rn(f.y),
                                __float2half_rn(f.z), __float2half_rn(f.w)};
    *(uint2*)(d + 4 * (size_t)i) = *(uint2*)h;
}

// ====================== mma.sync GEMM core ======================
// 128x128 CTA tile, BK=32, 128 threads, 4 warps (2x2), warp tile 64x64, 3-stage.
// A smem [M,K] (non-trans frags).  B smem [K,N] (trans frags).
#define SRA 80                         // A row stride bytes (32 halves + pad)
#define SRB2 272                       // B row stride bytes (128 halves + pad)
#define A_TILE (128 * SRA)             // 10240
#define B_TILE (32 * SRB2)             // 8704
#define STAGE_B (A_TILE + B_TILE)      // 18944
#define GEMM_SMEM (3 * STAGE_B)        // 56832
#define QKV_SMEM 66560                 // max(GEMM_SMEM, 128*130*4 epilogue stage)

struct AccT { float a[4][8][4]; };

__device__ __forceinline__ void gemm_core(
    uint32_t sbase, const __half* pA, const __half* pB, int Kd, int Nw, AccT& A)
{
    const int tid = threadIdx.x, lane = tid & 31, wid = tid >> 5;
    const int wm = wid >> 1, wn = wid & 1;

    const int nst = Kd >> 5;

    #pragma unroll
    for (int ps = 0; ps < 2; ps++) {       // prologue stages 0,1
        const int k0 = ps << 5;
        uint32_t st = sbase + ps * STAGE_B;
        #pragma unroll
        for (int i = 0; i < 4; i++) {      // A: 128 rows x 4 chunks
            int c = tid + 128 * i; int row = c >> 2, c16 = c & 3;
            CP16(st + (uint32_t)row * SRA + c16 * 16,
                 pA + (size_t)row * Kd + k0 + c16 * 8);
        }
        #pragma unroll
        for (int i = 0; i < 4; i++) {      // B: 32 rows x 16 chunks
            int c = tid + 128 * i; int row = c >> 4, c16 = c & 15;
            CP16(st + A_TILE + (uint32_t)row * SRB2 + c16 * 16,
                 pB + (size_t)(k0 + row) * Nw + c16 * 8);
        }
        CP_COMMIT();
    }

    int sidx = 0;
    for (int s = 0; s < nst; s++) {
        if (s + 1 < nst) { CP_WAIT(1); } else { CP_WAIT(0); }
        __syncthreads();                   // single barrier per stage

        if (s + 2 < nst) {
            const int k0 = (s + 2) << 5;
            int lidx = sidx - 1; if (lidx < 0) lidx += 3;
            uint32_t st = sbase + lidx * STAGE_B;
            #pragma unroll
            for (int i = 0; i < 4; i++) {
                int c = tid + 128 * i; int row = c >> 2, c16 = c & 3;
                CP16(st + (uint32_t)row * SRA + c16 * 16,
                     pA + (size_t)row * Kd + k0 + c16 * 8);
            }
            #pragma unroll
            for (int i = 0; i < 4; i++) {
                int c = tid + 128 * i; int row = c >> 4, c16 = c & 15;
                CP16(st + A_TILE + (uint32_t)row * SRB2 + c16 * 16,
                     pB + (size_t)(k0 + row) * Nw + c16 * 8);
            }
            CP_COMMIT();
        }

        uint32_t st = sbase + sidx * STAGE_B;
        const uint32_t aAddr = st + (uint32_t)(wm * 64 + (lane & 15)) * SRA
                             + (lane >> 4) * 16;
        const uint32_t bAddr = st + A_TILE
                             + (uint32_t)(((lane >> 3) & 1) * 8 + (lane & 7)) * SRB2
                             + ((lane >> 4) & 1) * 16 + wn * 128;

        #pragma unroll
        for (int kk = 0; kk < 2; kk++) {
            uint32_t ah[4][4], bb[8][2];
            #pragma unroll
            for (int mt = 0; mt < 4; mt++)
                LDSM4(ah[mt], aAddr + mt * 16 * SRA + kk * 32);
            #pragma unroll
            for (int np = 0; np < 4; np++) {
                uint32_t r[4];
                LDSM4T(r, bAddr + kk * 16 * SRB2 + np * 32);
                bb[2*np][0] = r[0]; bb[2*np][1] = r[1];
                bb[2*np+1][0] = r[2]; bb[2*np+1][1] = r[3];
            }
            #pragma unroll
            for (int mt = 0; mt < 4; mt++)
                #pragma unroll
                for (int nt = 0; nt < 8; nt++)
                    MMAH(A.a[mt][nt], ah[mt], bb[nt]);
        }
        if (++sidx == 3) sidx = 0;
    }
}

// ---- merged QKV projection + fused RoPE: grid (48, 16), 128 threads ----
__global__ __launch_bounds__(128) void gemm_qkv(
    const __half* __restrict__ Ah,
    const __half* __restrict__ WQ, const __half* __restrict__ WK,
    const __half* __restrict__ WV, const int* __restrict__ pos,
    __half* __restrict__ Qh, __half* __restrict__ Kh, __half* __restrict__ Vh)
{
    extern __shared__ char smraw[];
    const uint32_t sbase = smem_to_u32(smraw);
    const int bx = blockIdx.x;
    const int Kd = DD;

    const __half* pB;
    int bn, kind, Nw;   // kind 0=q(rope), 1=k(rope), 2=v(fp16 direct)
    if (bx < 32)      { pB = WQ; bn = bx;      kind = 0; Nw = NH * HD; }
    else if (bx < 40) { pB = WK; bn = bx - 32; kind = 1; Nw = KH * HD; }
    else              { pB = WV; bn = bx - 40; kind = 2; Nw = KH * HD; }
    pB += (size_t)bn * 128;

    AccT A;
    #pragma unroll
    for (int mt = 0; mt < 4; mt++)
        #pragma unroll
        for (int nt = 0; nt < 8; nt++)
            #pragma unroll
            for (int q = 0; q < 4; q++) A.a[mt][nt][q] = 0.f;

    gemm_core(sbase, Ah + (size_t)blockIdx.y * 128 * Kd, pB, Kd, Nw, A);

    const int tid = threadIdx.x;
    const int lane = tid & 31, wid = tid >> 5;
    const int wm = wid >> 1, wn = wid & 1;

    if (kind == 2) {
        const int rb = blockIdx.y * 128 + wm * 64 + (lane >> 2);
        const int cbl = bn * 128 + wn * 64 + (lane & 3) * 2;
        #pragma unroll
        for (int mt = 0; mt < 4; mt++)
            #pragma unroll
            for (int nt = 0; nt < 8; nt++) {
                const int row = rb + mt * 16;
                const int col = cbl + nt * 8;
                *(__half2*)(Vh + (size_t)row * (KH*HD) + col) =
                    __floats2half2_rn(A.a[mt][nt][0], A.a[mt][nt][1]);
                *(__half2*)(Vh + (size_t)(row + 8) * (KH*HD) + col) =
                    __floats2half2_rn(A.a[mt][nt][2], A.a[mt][nt][3]);
            }
        return;
    }

    // ---- fused RoPE: stage fp32 tile in smem, rotate pairs (c, c+64) ----
    __syncthreads();                   // all warps done reading stage smem
    float* sm = (float*)smraw;         // [128][130]
    #pragma unroll
    for (int mt = 0; mt < 4; mt++)
        #pragma unroll
        for (int nt = 0; nt < 8; nt++) {
            const int rl = wm * 64 + mt * 16 + (lane >> 2);
            const int cl = wn * 64 + nt * 8 + (lane & 3) * 2;
            *(float2*)&sm[rl * 130 + cl] = make_float2(A.a[mt][nt][0], A.a[mt][nt][1]);
            *(float2*)&sm[(rl + 8) * 130 + cl] = make_float2(A.a[mt][nt][2], A.a[mt][nt][3]);
        }
    __syncthreads();

    const float scale = (kind == 0) ? SCALE : 1.0f;
    __half* dst = (kind == 0) ? Qh : Kh;
    const int HEADS = (kind == 0) ? NH : KH;
    const int c = tid & 63;
    const int rbase = tid >> 6;        // 0..1
    const float e = (float)c * (1.0f / 64.0f);
    const float invf = 1.0f / powf(10000.0f, e);

    #pragma unroll 4
    for (int i = 0; i < 64; i++) {
        const int row = i * 2 + rbase;
        const int t = blockIdx.y * 128 + row;
        float sn, cs;
        sincosf((float)pos[t] * invf, &sn, &cs);
        const float x1 = sm[row * 130 + c];
        const float x2 = sm[row * 130 + c + 64];
        const size_t o = ((size_t)t * HEADS + bn) * HD + c;
        dst[o]      = __float2half_rn((x1 * cs - x2 * sn) * scale);
        dst[o + 64] = __float2half_rn((x2 * cs + x1 * sn) * scale);
    }
}

// ---- o-proj: C fp32, grid (32, 16), 128 threads ----
__global__ __launch_bounds__(128) void gemm_o(
    const __half* __restrict__ Ah, const __half* __restrict__ B,
    float* __restrict__ C)
{
    extern __shared__ char smraw[];
    const uint32_t sbase = smem_to_u32(smraw);
    const int Kd = DD, N = DD;

    AccT A;
    #pragma unroll
    for (int mt = 0; mt < 4; mt++)
        #pragma unroll
        for (int nt = 0; nt < 8; nt++)
            #pragma unroll
            for (int q = 0; q < 4; q++) A.a[mt][nt][q] = 0.f;

    gemm_core(sbase, Ah + (size_t)blockIdx.y * 128 * Kd,
              B + (size_t)blockIdx.x * 128, Kd, N, A);

    const int lane = threadIdx.x & 31, wid = threadIdx.x >> 5;
    const int wm = wid >> 1, wn = wid & 1;
    const int rb = blockIdx.y * 128 + wm * 64 + (lane >> 2);
    const int cb = blockIdx.x * 128 + wn * 64 + (lane & 3) * 2;
    #pragma unroll
    for (int mt = 0; mt < 4; mt++)
        #pragma unroll
        for (int nt = 0; nt < 8; nt++) {
            const int row = rb + mt * 16;
            const int col = cb + nt * 8;
            *(float2*)(C + (size_t)row * N + col) =
                make_float2(A.a[mt][nt][0], A.a[mt][nt][1]);
            *(float2*)(C + (size_t)(row + 8) * N + col) =
                make_float2(A.a[mt][nt][2], A.a[mt][nt][3]);
        }
}

// ====================== HMMA flash attention (causal, GQA) ======================
// CTA: 128 q rows x 1 head, 8 warps (16 q rows each). KV tiles of 64, 3 stages.
#define SRB 272
#define FL_STAGE (2 * 64 * SRB)        // K + V per tile = 34816
#define FL_SMEM (3 * FL_STAGE)         // 104448

__global__ __launch_bounds__(256) void flash_h(
    const __half* __restrict__ Qv, const __half* __restrict__ Kv,
    const __half* __restrict__ Vv, __half* __restrict__ Oh)
{
    extern __shared__ char fsm[];
    const uint32_t uSt = smem_to_u32(fsm);

    const int tid = threadIdx.x, lane = tid & 31, wid = tid >> 5;
    const int qi = gridDim.x - 1 - blockIdx.x;     // heavy tiles first
    const int n = blockIdx.y, kvh = n >> 2;
    const int tq0 = qi * 128;
    const int ntiles = 2 * qi + 2;

    const __half* Qg = Qv + ((size_t)tq0 * NH + n) * HD;
    const __half* Kg = Kv + (size_t)kvh * HD;
    const __half* Vg = Vv + (size_t)kvh * HD;

    // ---- stage Q into stage-0 area, read frags ----
    #pragma unroll
    for (int i = 0; i < 8; i++) {
        int c = tid + 256 * i;
        int row = c >> 4, c16 = c & 15;
        CP16(uSt + (uint32_t)row * SRB + c16 * 16,
             Qg + (size_t)row * (NH * HD) + c16 * 8);
    }
    CP_COMMIT();
    CP_WAIT(0);
    __syncthreads();

    uint32_t qh[8][4];
    {
        const uint32_t qa = uSt + (uint32_t)(wid * 16 + (lane & 15)) * SRB
                          + (lane >> 4) * 16;
        #pragma unroll
        for (int dc = 0; dc < 8; dc++)
            LDSM4(qh[dc], qa + dc * 32);
    }
    __syncthreads();   // stage area free for KV

    // paired ldmatrix lane offsets
    const uint32_t kOff = (uint32_t)((lane >> 4) * 8 + (lane & 7)) * SRB
                        + ((lane >> 3) & 1) * 16;
    const uint32_t vOff = (uint32_t)(((lane >> 3) & 1) * 8 + (lane & 7)) * SRB
                        + ((lane >> 4) & 1) * 16;

    float o[16][4];
    #pragma unroll
    for (int i = 0; i < 16; i++)
        #pragma unroll
        for (int j = 0; j < 4; j++) o[i][j] = 0.f;
    float m0 = -1e30f, m1 = -1e30f, l0 = 0.f, l1 = 0.f;

    // preload tiles 0 and 1 (ntiles >= 2 always)
    #pragma unroll
    for (int ps = 0; ps < 2; ps++) {
        uint32_t st = uSt + ps * FL_STAGE;
        const int s0 = ps * 64;
        #pragma unroll
        for (int i = 0; i < 4; i++) {
            int c = tid + 256 * i;
            int row = c >> 4, c16 = c & 15;
            size_t go = (size_t)(s0 + row) * (KH * HD) + c16 * 8;
            CP16(st + (uint32_t)row * SRB + c16 * 16, Kg + go);
            CP16(st + 64 * SRB + (uint32_t)row * SRB + c16 * 16, Vg + go);
        }
        CP_COMMIT();
    }

    int sidx = 0;
    for (int t = 0; t < ntiles; t++) {
        if (t + 1 < ntiles) { CP_WAIT(1); } else { CP_WAIT(0); }
        __syncthreads();                 // tile t visible; stage (t+2)%3 free

        if (t + 2 < ntiles) {
            int lidx = sidx - 1; if (lidx < 0) lidx += 3;
            uint32_t st = uSt + lidx * FL_STAGE;
            const int s0 = (t + 2) * 64;
            #pragma unroll
            for (int i = 0; i < 4; i++) {
                int c = tid + 256 * i;
                int row = c >> 4, c16 = c & 15;
                size_t go = (size_t)(s0 + row) * (KH * HD) + c16 * 8;
                CP16(st + (uint32_t)row * SRB + c16 * 16, Kg + go);
                CP16(st + 64 * SRB + (uint32_t)row * SRB + c16 * 16, Vg + go);
            }
            CP_COMMIT();
        }

        const uint32_t uK = uSt + sidx * FL_STAGE;
        const uint32_t uV = uK + 64 * SRB;

        // ---- S = Q K^T ----
        float s[8][4];
        #pragma unroll
        for (int nt = 0; nt < 8; nt++)
            #pragma unroll
            for (int j = 0; j < 4; j++) s[nt][j] = 0.f;

        #pragma unroll
        for (int dc = 0; dc < 8; dc++) {
            #pragma unroll
            for (int ntp = 0; ntp < 4; ntp++) {
                uint32_t r[4];
                LDSM4(r, uK + kOff + (uint32_t)ntp * 16 * SRB + dc * 32);
                uint32_t b0[2] = {r[0], r[1]}, b1[2] = {r[2], r[3]};
                MMAH(s[2*ntp],     qh[dc], b0);
                MMAH(s[2*ntp + 1], qh[dc], b1);
            }
        }

        // ---- causal mask ----
        if (t >= 2 * qi) {
            const int r0 = tq0 + wid * 16 + (lane >> 2);
            const int cB = t * 64 + (lane & 3) * 2;
            #pragma unroll
            for (int nt = 0; nt < 8; nt++) {
                int c0 = cB + nt * 8;
                if (c0     > r0)     s[nt][0] = -1e30f;
                if (c0 + 1 > r0)     s[nt][1] = -1e30f;
                if (c0     > r0 + 8) s[nt][2] = -1e30f;
                if (c0 + 1 > r0 + 8) s[nt][3] = -1e30f;
            }
        }

        // ---- online softmax ----
        float mr0 = -1e30f, mr1 = -1e30f;
        #pragma unroll
        for (int nt = 0; nt < 8; nt++) {
            mr0 = fmaxf(mr0, fmaxf(s[nt][0], s[nt][1]));
            mr1 = fmaxf(mr1, fmaxf(s[nt][2], s[nt][3]));
        }
        mr0 = fmaxf(mr0, __shfl_xor_sync(0xffffffffu, mr0, 1));
        mr0 = fmaxf(mr0, __shfl_xor_sync(0xffffffffu, mr0, 2));
        mr1 = fmaxf(mr1, __shfl_xor_sync(0xffffffffu, mr1, 1));
        mr1 = fmaxf(mr1, __shfl_xor_sync(0xffffffffu, mr1, 2));

        const float mn0 = fmaxf(m0, mr0), mn1 = fmaxf(m1, mr1);
        const float a0 = __expf(m0 - mn0), a1 = __expf(m1 - mn1);
        m0 = mn0; m1 = mn1;

        float ls0 = 0.f, ls1 = 0.f;
        #pragma unroll
        for (int nt = 0; nt < 8; nt++) {
            s[nt][0] = __expf(s[nt][0] - m0); ls0 += s[nt][0];
            s[nt][1] = __expf(s[nt][1] - m0); ls0 += s[nt][1];
            s[nt][2] = __expf(s[nt][2] - m1); ls1 += s[nt][2];
            s[nt][3] = __expf(s[nt][3] - m1); ls1 += s[nt][3];
        }
        ls0 += __shfl_xor_sync(0xffffffffu, ls0, 1);
        ls0 += __shfl_xor_sync(0xffffffffu, ls0, 2);
        ls1 += __shfl_xor_sync(0xffffffffu, ls1, 1);
        ls1 += __shfl_xor_sync(0xffffffffu, ls1, 2);
        l0 = l0 * a0 + ls0;
        l1 = l1 * a1 + ls1;

        #pragma unroll
        for (int i = 0; i < 16; i++) {
            o[i][0] *= a0; o[i][1] *= a0; o[i][2] *= a1; o[i][3] *= a1;
        }

        // ---- P fragments (single fp16) ----
        uint32_t phi[4][4];
        #pragma unroll
        for (int kc = 0; kc < 4; kc++) {
            #pragma unroll
            for (int q = 0; q < 4; q++) {
                int nt = 2 * kc + (q >> 1);
                __half2 h = __floats2half2_rn(s[nt][(q & 1) * 2],
                                              s[nt][(q & 1) * 2 + 1]);
                phi[kc][q] = *(uint32_t*)&h;
            }
        }

        // ---- O += P V ----
        #pragma unroll
        for (int np = 0; np < 8; np++) {
            #pragma unroll
            for (int kc = 0; kc < 4; kc++) {
                uint32_t r[4];
                LDSM4T(r, uV + vOff + (uint32_t)kc * 16 * SRB + np * 32);
                uint32_t b0[2] = {r[0], r[1]}, b1[2] = {r[2], r[3]};
                MMAH(o[2*np],     phi[kc], b0);
                MMAH(o[2*np + 1], phi[kc], b1);
            }
        }
        if (++sidx == 3) sidx = 0;
    }

    // ---- epilogue: O / l, write single fp16 ----
    const float i0 = 1.f / l0, i1 = 1.f / l1;
    const int r0 = tq0 + wid * 16 + (lane >> 2);
    const int cofs = (lane & 3) * 2;
    #pragma unroll
    for (int nt2 = 0; nt2 < 16; nt2++) {
        float v0 = o[nt2][0] * i0, v1 = o[nt2][1] * i0;
        float v2 = o[nt2][2] * i1, v3 = o[nt2][3] * i1;
        size_t p0 = ((size_t)r0 * NH + n) * HD + nt2 * 8 + cofs;
        size_t p1 = ((size_t)(r0 + 8) * NH + n) * HD + nt2 * 8 + cofs;
        *(__half2*)(Oh + p0) = __floats2half2_rn(v0, v1);
        *(__half2*)(Oh + p1) = __floats2half2_rn(v2, v3);
    }
}

// ====================== launch ======================
extern "C" void kernel_launch(void* const* d_in, const int* in_sizes, int n_in,
                              void* d_out, int out_size)
{
    const float* x   = (const float*)d_in[0];
    const int*   pos = (const int*)  d_in[1];
    const float* w_q = (const float*)d_in[2];
    const float* w_k = (const float*)d_in[3];
    const float* w_v = (const float*)d_in[4];
    const float* w_o = (const float*)d_in[5];
    float* out = (float*)d_out;

    __half *xh, *aoh, *wq16, *wk16, *wv16, *wo16, *qh, *kh, *vh;
    cudaGetSymbolAddress((void**)&xh,   g_xh);
    cudaGetSymbolAddress((void**)&aoh,  g_aoh);
    cudaGetSymbolAddress((void**)&wq16, g_wq16); cudaGetSymbolAddress((void**)&wk16, g_wk16);
    cudaGetSymbolAddress((void**)&wv16, g_wv16); cudaGetSymbolAddress((void**)&wo16, g_wo16);
    cudaGetSymbolAddress((void**)&qh,   g_qh);
    cudaGetSymbolAddress((void**)&kh,   g_kh);   cudaGetSymbolAddress((void**)&vh,   g_vh);

    cudaFuncSetAttribute(gemm_qkv, cudaFuncAttributeMaxDynamicSharedMemorySize, QKV_SMEM);
    cudaFuncSetAttribute(gemm_o,   cudaFuncAttributeMaxDynamicSharedMemorySize, GEMM_SMEM);
    cudaFuncSetAttribute(flash_h,  cudaFuncAttributeMaxDynamicSharedMemorySize, FL_SMEM);

    // fused fp16 conversions (x + all weights)
    conv_all<<<(F4_TOT + 255)/256, 256>>>(x, w_q, w_k, w_v, w_o,
                                          xh, wq16, wk16, wv16, wo16);

    // merged QKV projection + fused RoPE (128x128 tiles, 4 warps of 64x64)
    gemm_qkv<<<dim3(48, 16), 128, QKV_SMEM>>>(xh, wq16, wk16, wv16, pos, qh, kh, vh);

    // causal GQA flash attention (HMMA, 3-stage KV pipeline)
    flash_h<<<dim3(TT/128, NH), 256, FL_SMEM>>>(qh, kh, vh, aoh);

    // output projection (128x128 tiles, 4 warps of 64x64)
    gemm_o<<<dim3(32, 16), 128, GEMM_SMEM>>>(aoh, wo16, out);
}

// round 16
// speedup vs baseline: 1.1327x; 1.0560x over previous
#include <cuda_runtime.h>
#include <cuda_fp16.h>
#include <cstdint>
#include <math.h>

// Problem constants
#define TT 2048
#define DD 4096
#define NH 32
#define KH 8
#define HD 128
#define SCALE 0.08838834764831843f   // 1/sqrt(128)

// ====================== PTX helpers (base sm_103-legal only) ======================
__device__ __forceinline__ uint32_t smem_to_u32(const void* p) {
    uint32_t a;
    asm("{ .reg .u64 t; cvta.to.shared.u64 t, %1; cvt.u32.u64 %0, t; }" : "=r"(a) : "l"(p));
    return a;
}
#define CP16(sa, ga) \
    asm volatile("cp.async.cg.shared.global [%0], [%1], 16;" :: "r"(sa), "l"(ga) : "memory")
#define CP_COMMIT() asm volatile("cp.async.commit_group;" ::: "memory")
#define CP_WAIT(n)  asm volatile("cp.async.wait_group %0;" :: "n"(n) : "memory")
#define LDSM4(r, a) \
    asm volatile("ldmatrix.sync.aligned.m8n8.x4.shared.b16 {%0,%1,%2,%3}, [%4];" \
        : "=r"((r)[0]), "=r"((r)[1]), "=r"((r)[2]), "=r"((r)[3]) : "r"(a))
#define LDSM4T(r, a) \
    asm volatile("ldmatrix.sync.aligned.m8n8.x4.trans.shared.b16 {%0,%1,%2,%3}, [%4];" \
        : "=r"((r)[0]), "=r"((r)[1]), "=r"((r)[2]), "=r"((r)[3]) : "r"(a))
#define MMAH(d, a, b) \
    asm volatile("mma.sync.aligned.m16n8k16.row.col.f32.f16.f16.f32 " \
        "{%0,%1,%2,%3}, {%4,%5,%6,%7}, {%8,%9}, {%0,%1,%2,%3};" \
        : "+f"((d)[0]), "+f"((d)[1]), "+f"((d)[2]), "+f"((d)[3]) \
        : "r"((a)[0]), "r"((a)[1]), "r"((a)[2]), "r"((a)[3]), "r"((b)[0]), "r"((b)[1]))

// ====================== device scratch ======================
__device__ __half g_xh  [TT * DD];
__device__ __half g_aoh [TT * DD];
__device__ __half g_wq16[DD * DD];       // fp16 copy, natural [K,N] layout
__device__ __half g_wk16[DD * KH*HD];
__device__ __half g_wv16[DD * KH*HD];
__device__ __half g_wo16[DD * DD];
__device__ __half g_qh  [TT * NH * HD];
__device__ __half g_kh  [TT * KH * HD];
__device__ __half g_vh  [TT * KH * HD];

// ====================== fused fp32 -> fp16 convert (x, wq, wk, wv) ============
// 8388608 float4 total, 4 per thread via segment-aligned strides (ILP=4).
#define F4_SEG 2097152     // stride = total/4

__device__ __forceinline__ void cvt4(const float* __restrict__ s,
                                     __half* __restrict__ d, long long i)
{
    float4 f = ((const float4*)s)[i];
    __align__(8) __half h[4] = {__float2half_rn(f.x), __float2half_rn(f.y),
                                __float2half_rn(f.z), __float2half_rn(f.w)};
    *(uint2*)(d + 4 * (size_t)i) = *(uint2*)h;
}

__global__ void conv_xw(
    const float* __restrict__ x,  const float* __restrict__ wq,
    const float* __restrict__ wk, const float* __restrict__ wv,
    __half* __restrict__ xh, __half* __restrict__ wqh,
    __half* __restrict__ wkh, __half* __restrict__ wvh)
{
    const int idx = blockIdx.x * 256 + threadIdx.x;     // 0..2097151
    cvt4(x,  xh,  idx);                                 // seg 0: x (exact)
    cvt4(wq, wqh, idx);                                 // seg 1: wq half 1
    cvt4(wq, wqh, idx + F4_SEG);                        // seg 2: wq half 2
    if (idx < 1048576) cvt4(wk, wkh, idx);              // seg 3: wk | wv
    else               cvt4(wv, wvh, idx - 1048576);
}

// ====================== mma.sync GEMM core ======================
// 128x128 CTA tile, BK=32, 128 threads, 4 warps (2x2), warp tile 64x64, 3-stage.
#define SRA 80                         // A row stride bytes (32 halves + pad)
#define SRB2 272                       // B row stride bytes (128 halves + pad)
#define A_TILE (128 * SRA)             // 10240
#define B_TILE (32 * SRB2)             // 8704
#define STAGE_B (A_TILE + B_TILE)      // 18944
#define GEMM_SMEM (3 * STAGE_B)        // 56832
#define QKV_SMEM 66560                 // max(GEMM_SMEM, 128*130*4 epilogue stage)

struct AccT { float a[4][8][4]; };

__device__ __forceinline__ void gemm_core(
    uint32_t sbase, const __half* pA, const __half* pB, int Kd, int Nw, AccT& A)
{
    const int tid = threadIdx.x, lane = tid & 31, wid = tid >> 5;
    const int wm = wid >> 1, wn = wid & 1;

    const int nst = Kd >> 5;

    #pragma unroll
    for (int ps = 0; ps < 2; ps++) {       // prologue stages 0,1
        const int k0 = ps << 5;
        uint32_t st = sbase + ps * STAGE_B;
        #pragma unroll
        for (int i = 0; i < 4; i++) {      // A: 128 rows x 4 chunks
            int c = tid + 128 * i; int row = c >> 2, c16 = c & 3;
            CP16(st + (uint32_t)row * SRA + c16 * 16,
                 pA + (size_t)row * Kd + k0 + c16 * 8);
        }
        #pragma unroll
        for (int i = 0; i < 4; i++) {      // B: 32 rows x 16 chunks
            int c = tid + 128 * i; int row = c >> 4, c16 = c & 15;
            CP16(st + A_TILE + (uint32_t)row * SRB2 + c16 * 16,
                 pB + (size_t)(k0 + row) * Nw + c16 * 8);
        }
        CP_COMMIT();
    }

    int sidx = 0;
    for (int s = 0; s < nst; s++) {
        if (s + 1 < nst) { CP_WAIT(1); } else { CP_WAIT(0); }
        __syncthreads();                   // single barrier per stage

        if (s + 2 < nst) {
            const int k0 = (s + 2) << 5;
            int lidx = sidx - 1; if (lidx < 0) lidx += 3;
            uint32_t st = sbase + lidx * STAGE_B;
            #pragma unroll
            for (int i = 0; i < 4; i++) {
                int c = tid + 128 * i; int row = c >> 2, c16 = c & 3;
                CP16(st + (uint32_t)row * SRA + c16 * 16,
                     pA + (size_t)row * Kd + k0 + c16 * 8);
            }
            #pragma unroll
            for (int i = 0; i < 4; i++) {
                int c = tid + 128 * i; int row = c >> 4, c16 = c & 15;
                CP16(st + A_TILE + (uint32_t)row * SRB2 + c16 * 16,
                     pB + (size_t)(k0 + row) * Nw + c16 * 8);
            }
            CP_COMMIT();
        }

        uint32_t st = sbase + sidx * STAGE_B;
        const uint32_t aAddr = st + (uint32_t)(wm * 64 + (lane & 15)) * SRA
                             + (lane >> 4) * 16;
        const uint32_t bAddr = st + A_TILE
                             + (uint32_t)(((lane >> 3) & 1) * 8 + (lane & 7)) * SRB2
                             + ((lane >> 4) & 1) * 16 + wn * 128;

        #pragma unroll
        for (int kk = 0; kk < 2; kk++) {
            uint32_t ah[4][4], bb[8][2];
            #pragma unroll
            for (int mt = 0; mt < 4; mt++)
                LDSM4(ah[mt], aAddr + mt * 16 * SRA + kk * 32);
            #pragma unroll
            for (int np = 0; np < 4; np++) {
                uint32_t r[4];
                LDSM4T(r, bAddr + kk * 16 * SRB2 + np * 32);
                bb[2*np][0] = r[0]; bb[2*np][1] = r[1];
                bb[2*np+1][0] = r[2]; bb[2*np+1][1] = r[3];
            }
            #pragma unroll
            for (int mt = 0; mt < 4; mt++)
                #pragma unroll
                for (int nt = 0; nt < 8; nt++)
                    MMAH(A.a[mt][nt], ah[mt], bb[nt]);
        }
        if (++sidx == 3) sidx = 0;
    }
}

// ---- merged QKV projection + fused RoPE: grid (48, 16), 128 threads ----
__global__ __launch_bounds__(128) void gemm_qkv(
    const __half* __restrict__ Ah,
    const __half* __restrict__ WQ, const __half* __restrict__ WK,
    const __half* __restrict__ WV, const int* __restrict__ pos,
    __half* __restrict__ Qh, __half* __restrict__ Kh, __half* __restrict__ Vh)
{
    extern __shared__ char smraw[];
    const uint32_t sbase = smem_to_u32(smraw);
    const int bx = blockIdx.x;
    const int Kd = DD;

    const __half* pB;
    int bn, kind, Nw;   // kind 0=q(rope), 1=k(rope), 2=v(fp16 direct)
    if (bx < 32)      { pB = WQ; bn = bx;      kind = 0; Nw = NH * HD; }
    else if (bx < 40) { pB = WK; bn = bx - 32; kind = 1; Nw = KH * HD; }
    else              { pB = WV; bn = bx - 40; kind = 2; Nw = KH * HD; }
    pB += (size_t)bn * 128;

    AccT A;
    #pragma unroll
    for (int mt = 0; mt < 4; mt++)
        #pragma unroll
        for (int nt = 0; nt < 8; nt++)
            #pragma unroll
            for (int q = 0; q < 4; q++) A.a[mt][nt][q] = 0.f;

    gemm_core(sbase, Ah + (size_t)blockIdx.y * 128 * Kd, pB, Kd, Nw, A);

    const int tid = threadIdx.x;
    const int lane = tid & 31, wid = tid >> 5;
    const int wm = wid >> 1, wn = wid & 1;

    if (kind == 2) {
        const int rb = blockIdx.y * 128 + wm * 64 + (lane >> 2);
        const int cbl = bn * 128 + wn * 64 + (lane & 3) * 2;
        #pragma unroll
        for (int mt = 0; mt < 4; mt++)
            #pragma unroll
            for (int nt = 0; nt < 8; nt++) {
                const int row = rb + mt * 16;
                const int col = cbl + nt * 8;
                *(__half2*)(Vh + (size_t)row * (KH*HD) + col) =
                    __floats2half2_rn(A.a[mt][nt][0], A.a[mt][nt][1]);
                *(__half2*)(Vh + (size_t)(row + 8) * (KH*HD) + col) =
                    __floats2half2_rn(A.a[mt][nt][2], A.a[mt][nt][3]);
            }
        return;
    }

    // ---- fused RoPE: stage fp32 tile in smem, rotate pairs (c, c+64) ----
    __syncthreads();                   // all warps done reading stage smem
    float* sm = (float*)smraw;         // [128][130]
    #pragma unroll
    for (int mt = 0; mt < 4; mt++)
        #pragma unroll
        for (int nt = 0; nt < 8; nt++) {
            const int rl = wm * 64 + mt * 16 + (lane >> 2);
            const int cl = wn * 64 + nt * 8 + (lane & 3) * 2;
            *(float2*)&sm[rl * 130 + cl] = make_float2(A.a[mt][nt][0], A.a[mt][nt][1]);
            *(float2*)&sm[(rl + 8) * 130 + cl] = make_float2(A.a[mt][nt][2], A.a[mt][nt][3]);
        }
    __syncthreads();

    const float scale = (kind == 0) ? SCALE : 1.0f;
    __half* dst = (kind == 0) ? Qh : Kh;
    const int HEADS = (kind == 0) ? NH : KH;
    const int c = tid & 63;
    const int rbase = tid >> 6;        // 0..1
    const float e = (float)c * (1.0f / 64.0f);
    const float invf = 1.0f / powf(10000.0f, e);

    #pragma unroll 4
    for (int i = 0; i < 64; i++) {
        const int row = i * 2 + rbase;
        const int t = blockIdx.y * 128 + row;
        float sn, cs;
        sincosf((float)pos[t] * invf, &sn, &cs);
        const float x1 = sm[row * 130 + c];
        const float x2 = sm[row * 130 + c + 64];
        const size_t o = ((size_t)t * HEADS + bn) * HD + c;
        dst[o]      = __float2half_rn((x1 * cs - x2 * sn) * scale);
        dst[o + 64] = __float2half_rn((x2 * cs + x1 * sn) * scale);
    }
}

// ---- o-proj: C fp32, grid (32, 16), 128 threads ----
__global__ __launch_bounds__(128) void gemm_o(
    const __half* __restrict__ Ah, const __half* __restrict__ B,
    float* __restrict__ C)
{
    extern __shared__ char smraw[];
    const uint32_t sbase = smem_to_u32(smraw);
    const int Kd = DD, N = DD;

    AccT A;
    #pragma unroll
    for (int mt = 0; mt < 4; mt++)
        #pragma unroll
        for (int nt = 0; nt < 8; nt++)
            #pragma unroll
            for (int q = 0; q < 4; q++) A.a[mt][nt][q] = 0.f;

    gemm_core(sbase, Ah + (size_t)blockIdx.y * 128 * Kd,
              B + (size_t)blockIdx.x * 128, Kd, N, A);

    const int lane = threadIdx.x & 31, wid = threadIdx.x >> 5;
    const int wm = wid >> 1, wn = wid & 1;
    const int rb = blockIdx.y * 128 + wm * 64 + (lane >> 2);
    const int cb = blockIdx.x * 128 + wn * 64 + (lane & 3) * 2;
    #pragma unroll
    for (int mt = 0; mt < 4; mt++)
        #pragma unroll
        for (int nt = 0; nt < 8; nt++) {
            const int row = rb + mt * 16;
            const int col = cb + nt * 8;
            *(float2*)(C + (size_t)row * N + col) =
                make_float2(A.a[mt][nt][0], A.a[mt][nt][1]);
            *(float2*)(C + (size_t)(row + 8) * N + col) =
                make_float2(A.a[mt][nt][2], A.a[mt][nt][3]);
        }
}

// ====================== HMMA flash attention (causal, GQA) ======================
// 1D grid: [0,512) flash CTAs (128 q rows x 1 head, heavy-first),
// [512, 512+2048) w_o fp32->fp16 converter CTAs (fill the causal tail).
#define SRB 272
#define FL_STAGE (2 * 64 * SRB)        // K + V per tile = 34816
#define FL_SMEM (3 * FL_STAGE)         // 104448
#define FL_BLOCKS 512
#define WO_BLOCKS 2048                 // 2048 CTAs x 256 thr x 8 float4 = 4194304

__global__ __launch_bounds__(256) void flash_h(
    const __half* __restrict__ Qv, const __half* __restrict__ Kv,
    const __half* __restrict__ Vv, __half* __restrict__ Oh,
    const float* __restrict__ WoS, __half* __restrict__ WoD)
{
    // ---- tail-filling w_o converter CTAs ----
    if (blockIdx.x >= FL_BLOCKS) {
        const int j = blockIdx.x - FL_BLOCKS;
        const int base = j * 2048 + threadIdx.x;
        #pragma unroll
        for (int k = 0; k < 8; k++)
            cvt4(WoS, WoD, base + k * 256);
        return;
    }

    extern __shared__ char fsm[];
    const uint32_t uSt = smem_to_u32(fsm);

    const int tid = threadIdx.x, lane = tid & 31, wid = tid >> 5;
    const int n  = blockIdx.x & 31;                // head (KV-shared groups adjacent)
    const int qi = 15 - (blockIdx.x >> 5);         // heavy tiles first
    const int kvh = n >> 2;
    const int tq0 = qi * 128;
    const int ntiles = 2 * qi + 2;

    const __half* Qg = Qv + ((size_t)tq0 * NH + n) * HD;
    const __half* Kg = Kv + (size_t)kvh * HD;
    const __half* Vg = Vv + (size_t)kvh * HD;

    // ---- stage Q into stage-0 area, read frags ----
    #pragma unroll
    for (int i = 0; i < 8; i++) {
        int c = tid + 256 * i;
        int row = c >> 4, c16 = c & 15;
        CP16(uSt + (uint32_t)row * SRB + c16 * 16,
             Qg + (size_t)row * (NH * HD) + c16 * 8);
    }
    CP_COMMIT();
    CP_WAIT(0);
    __syncthreads();

    uint32_t qh[8][4];
    {
        const uint32_t qa = uSt + (uint32_t)(wid * 16 + (lane & 15)) * SRB
                          + (lane >> 4) * 16;
        #pragma unroll
        for (int dc = 0; dc < 8; dc++)
            LDSM4(qh[dc], qa + dc * 32);
    }
    __syncthreads();   // stage area free for KV

    // paired ldmatrix lane offsets
    const uint32_t kOff = (uint32_t)((lane >> 4) * 8 + (lane & 7)) * SRB
                        + ((lane >> 3) & 1) * 16;
    const uint32_t vOff = (uint32_t)(((lane >> 3) & 1) * 8 + (lane & 7)) * SRB
                        + ((lane >> 4) & 1) * 16;

    float o[16][4];
    #pragma unroll
    for (int i = 0; i < 16; i++)
        #pragma unroll
        for (int j = 0; j < 4; j++) o[i][j] = 0.f;
    float m0 = -1e30f, m1 = -1e30f, l0 = 0.f, l1 = 0.f;

    // preload tiles 0 and 1 (ntiles >= 2 always)
    #pragma unroll
    for (int ps = 0; ps < 2; ps++) {
        uint32_t st = uSt + ps * FL_STAGE;
        const int s0 = ps * 64;
        #pragma unroll
        for (int i = 0; i < 4; i++) {
            int c = tid + 256 * i;
            int row = c >> 4, c16 = c & 15;
            size_t go = (size_t)(s0 + row) * (KH * HD) + c16 * 8;
            CP16(st + (uint32_t)row * SRB + c16 * 16, Kg + go);
            CP16(st + 64 * SRB + (uint32_t)row * SRB + c16 * 16, Vg + go);
        }
        CP_COMMIT();
    }

    int sidx = 0;
    for (int t = 0; t < ntiles; t++) {
        if (t + 1 < ntiles) { CP_WAIT(1); } else { CP_WAIT(0); }
        __syncthreads();                 // tile t visible; stage (t+2)%3 free

        if (t + 2 < ntiles) {
            int lidx = sidx - 1; if (lidx < 0) lidx += 3;
            uint32_t st = uSt + lidx * FL_STAGE;
            const int s0 = (t + 2) * 64;
            #pragma unroll
            for (int i = 0; i < 4; i++) {
                int c = tid + 256 * i;
                int row = c >> 4, c16 = c & 15;
                size_t go = (size_t)(s0 + row) * (KH * HD) + c16 * 8;
                CP16(st + (uint32_t)row * SRB + c16 * 16, Kg + go);
                CP16(st + 64 * SRB + (uint32_t)row * SRB + c16 * 16, Vg + go);
            }
            CP_COMMIT();
        }

        const uint32_t uK = uSt + sidx * FL_STAGE;
        const uint32_t uV = uK + 64 * SRB;

        // ---- S = Q K^T ----
        float s[8][4];
        #pragma unroll
        for (int nt = 0; nt < 8; nt++)
            #pragma unroll
            for (int j = 0; j < 4; j++) s[nt][j] = 0.f;

        #pragma unroll
        for (int dc = 0; dc < 8; dc++) {
            #pragma unroll
            for (int ntp = 0; ntp < 4; ntp++) {
                uint32_t r[4];
                LDSM4(r, uK + kOff + (uint32_t)ntp * 16 * SRB + dc * 32);
                uint32_t b0[2] = {r[0], r[1]}, b1[2] = {r[2], r[3]};
                MMAH(s[2*ntp],     qh[dc], b0);
                MMAH(s[2*ntp + 1], qh[dc], b1);
            }
        }

        // ---- causal mask ----
        if (t >= 2 * qi) {
            const int r0 = tq0 + wid * 16 + (lane >> 2);
            const int cB = t * 64 + (lane & 3) * 2;
            #pragma unroll
            for (int nt = 0; nt < 8; nt++) {
                int c0 = cB + nt * 8;
                if (c0     > r0)     s[nt][0] = -1e30f;
                if (c0 + 1 > r0)     s[nt][1] = -1e30f;
                if (c0     > r0 + 8) s[nt][2] = -1e30f;
                if (c0 + 1 > r0 + 8) s[nt][3] = -1e30f;
            }
        }

        // ---- online softmax ----
        float mr0 = -1e30f, mr1 = -1e30f;
        #pragma unroll
        for (int nt = 0; nt < 8; nt++) {
            mr0 = fmaxf(mr0, fmaxf(s[nt][0], s[nt][1]));
            mr1 = fmaxf(mr1, fmaxf(s[nt][2], s[nt][3]));
        }
        mr0 = fmaxf(mr0, __shfl_xor_sync(0xffffffffu, mr0, 1));
        mr0 = fmaxf(mr0, __shfl_xor_sync(0xffffffffu, mr0, 2));
        mr1 = fmaxf(mr1, __shfl_xor_sync(0xffffffffu, mr1, 1));
        mr1 = fmaxf(mr1, __shfl_xor_sync(0xffffffffu, mr1, 2));

        const float mn0 = fmaxf(m0, mr0), mn1 = fmaxf(m1, mr1);
        const float a0 = __expf(m0 - mn0), a1 = __expf(m1 - mn1);
        m0 = mn0; m1 = mn1;

        float ls0 = 0.f, ls1 = 0.f;
        #pragma unroll
        for (int nt = 0; nt < 8; nt++) {
            s[nt][0] = __expf(s[nt][0] - m0); ls0 += s[nt][0];
            s[nt][1] = __expf(s[nt][1] - m0); ls0 += s[nt][1];
            s[nt][2] = __expf(s[nt][2] - m1); ls1 += s[nt][2];
            s[nt][3] = __expf(s[nt][3] - m1); ls1 += s[nt][3];
        }
        ls0 += __shfl_xor_sync(0xffffffffu, ls0, 1);
        ls0 += __shfl_xor_sync(0xffffffffu, ls0, 2);
        ls1 += __shfl_xor_sync(0xffffffffu, ls1, 1);
        ls1 += __shfl_xor_sync(0xffffffffu, ls1, 2);
        l0 = l0 * a0 + ls0;
        l1 = l1 * a1 + ls1;

        #pragma unroll
        for (int i = 0; i < 16; i++) {
            o[i][0] *= a0; o[i][1] *= a0; o[i][2] *= a1; o[i][3] *= a1;
        }

        // ---- P fragments (single fp16) ----
        uint32_t phi[4][4];
        #pragma unroll
        for (int kc = 0; kc < 4; kc++) {
            #pragma unroll
            for (int q = 0; q < 4; q++) {
                int nt = 2 * kc + (q >> 1);
                __half2 h = __floats2half2_rn(s[nt][(q & 1) * 2],
                                              s[nt][(q & 1) * 2 + 1]);
                phi[kc][q] = *(uint32_t*)&h;
            }
        }

        // ---- O += P V ----
        #pragma unroll
        for (int np = 0; np < 8; np++) {
            #pragma unroll
            for (int kc = 0; kc < 4; kc++) {
                uint32_t r[4];
                LDSM4T(r, uV + vOff + (uint32_t)kc * 16 * SRB + np * 32);
                uint32_t b0[2] = {r[0], r[1]}, b1[2] = {r[2], r[3]};
                MMAH(o[2*np],     phi[kc], b0);
                MMAH(o[2*np + 1], phi[kc], b1);
            }
        }
        if (++sidx == 3) sidx = 0;
    }

    // ---- epilogue: O / l, write single fp16 ----
    const float i0 = 1.f / l0, i1 = 1.f / l1;
    const int r0 = tq0 + wid * 16 + (lane >> 2);
    const int cofs = (lane & 3) * 2;
    #pragma unroll
    for (int nt2 = 0; nt2 < 16; nt2++) {
        float v0 = o[nt2][0] * i0, v1 = o[nt2][1] * i0;
        float v2 = o[nt2][2] * i1, v3 = o[nt2][3] * i1;
        size_t p0 = ((size_t)r0 * NH + n) * HD + nt2 * 8 + cofs;
        size_t p1 = ((size_t)(r0 + 8) * NH + n) * HD + nt2 * 8 + cofs;
        *(__half2*)(Oh + p0) = __floats2half2_rn(v0, v1);
        *(__half2*)(Oh + p1) = __floats2half2_rn(v2, v3);
    }
}

// ====================== launch ======================
extern "C" void kernel_launch(void* const* d_in, const int* in_sizes, int n_in,
                              void* d_out, int out_size)
{
    const float* x   = (const float*)d_in[0];
    const int*   pos = (const int*)  d_in[1];
    const float* w_q = (const float*)d_in[2];
    const float* w_k = (const float*)d_in[3];
    const float* w_v = (const float*)d_in[4];
    const float* w_o = (const float*)d_in[5];
    float* out = (float*)d_out;

    __half *xh, *aoh, *wq16, *wk16, *wv16, *wo16, *qh, *kh, *vh;
    cudaGetSymbolAddress((void**)&xh,   g_xh);
    cudaGetSymbolAddress((void**)&aoh,  g_aoh);
    cudaGetSymbolAddress((void**)&wq16, g_wq16); cudaGetSymbolAddress((void**)&wk16, g_wk16);
    cudaGetSymbolAddress((void**)&wv16, g_wv16); cudaGetSymbolAddress((void**)&wo16, g_wo16);
    cudaGetSymbolAddress((void**)&qh,   g_qh);
    cudaGetSymbolAddress((void**)&kh,   g_kh);   cudaGetSymbolAddress((void**)&vh,   g_vh);

    cudaFuncSetAttribute(gemm_qkv, cudaFuncAttributeMaxDynamicSharedMemorySize, QKV_SMEM);
    cudaFuncSetAttribute(gemm_o,   cudaFuncAttributeMaxDynamicSharedMemorySize, GEMM_SMEM);
    cudaFuncSetAttribute(flash_h,  cudaFuncAttributeMaxDynamicSharedMemorySize, FL_SMEM);

    // fused fp16 conversions for x + QKV weights (ILP=4 per thread)
    conv_xw<<<8192, 256>>>(x, w_q, w_k, w_v, xh, wq16, wk16, wv16);

    // merged QKV projection + fused RoPE (128x128 tiles, 4 warps of 64x64)
    gemm_qkv<<<dim3(48, 16), 128, QKV_SMEM>>>(xh, wq16, wk16, wv16, pos, qh, kh, vh);

    // flash attention + tail-filling w_o conversion (1D grid, heavy-first)
    flash_h<<<FL_BLOCKS + WO_BLOCKS, 256, FL_SMEM>>>(qh, kh, vh, aoh, w_o, wo16);

    // output projection (128x128 tiles, 4 warps of 64x64)
    gemm_o<<<dim3(32, 16), 128, GEMM_SMEM>>>(aoh, wo16, out);
}